// round 3
// baseline (speedup 1.0000x reference)
#include <cuda_runtime.h>
#include <cstdint>
#include <cstddef>

#define HH 1024
#define VV 50257
#define BB 64
#define TT 2048

// ---------------- scratch (device globals: no allocation) ----------------
__device__ float g_x[BB * 2 * HH];          // [B,2H] concat(embedded, context)
__device__ float g_gi[BB * 3 * HH];
__device__ float g_gh[BB * 3 * HH];
__device__ float g_h0[BB * HH];
__device__ float g_h1[BB * HH];
__device__ float g_u[BB * HH];              // output @ Wa
__device__ float g_scores[BB * TT];
__device__ float g_ctxpart[(size_t)BB * 64 * HH];   // 16.8 MB
__device__ float g_mpart[BB * 64];
__device__ float g_lpart[BB * 64];
__device__ float g_M[BB];
__device__ float g_L[BB];
__device__ float g_y[BB * 2 * HH];          // [B,2H] concat(output, context)
__device__ float g_logits[(size_t)BB * VV];
__device__ float g_lse[BB];

// ---------------- helpers ----------------
__device__ __forceinline__ uint32_t f2tf32(float f) {
    uint32_t u;
    asm("cvt.rna.tf32.f32 %0, %1;" : "=r"(u) : "f"(f));
    return u;
}

__device__ __forceinline__ void mma_tf32(float c[4], uint32_t a0, uint32_t a1,
                                         uint32_t a2, uint32_t a3,
                                         uint32_t b0, uint32_t b1) {
    asm volatile(
        "mma.sync.aligned.m16n8k8.row.col.f32.tf32.tf32.f32 "
        "{%0,%1,%2,%3}, {%4,%5,%6,%7}, {%8,%9}, {%0,%1,%2,%3};"
        : "+f"(c[0]), "+f"(c[1]), "+f"(c[2]), "+f"(c[3])
        : "r"(a0), "r"(a1), "r"(a2), "r"(a3), "r"(b0), "r"(b1));
}

// split fp32 -> (hi, lo) tf32 pair for 3xTF32 precise mma
__device__ __forceinline__ void split_tf32(float a, uint32_t& hi, uint32_t& lo) {
    hi = f2tf32(a);
    float r = a - __uint_as_float(hi);
    lo = f2tf32(r);
}

// ---------------- K1: x = concat(E[inputs], context) ----------------
__global__ __launch_bounds__(256) void build_x_kernel(
        const int* __restrict__ inputs,
        const float* __restrict__ E,
        const float* __restrict__ context) {
    int idx = blockIdx.x * blockDim.x + threadIdx.x;  // B*2H = 131072
    int b = idx >> 11;
    int j = idx & 2047;
    float v;
    if (j < HH) v = E[(size_t)inputs[b] * HH + j];
    else        v = context[b * HH + (j - HH)];
    g_x[idx] = v;
}

// ---------------- fast 64xN GEMM (1xTF32): C = X @ W^T + bias ----------------
// Used only for the logits GEMM (validated rel err 4.6e-5).
template <bool ACT_TANH>
__global__ __launch_bounds__(256) void gemm64_kernel(
        const float* __restrict__ X,
        const float* __restrict__ W,
        const float* __restrict__ bias,
        float* __restrict__ C, int N, int K) {
    __shared__ uint32_t As[64][65];  // [m][k], TILE_K = 64
    __shared__ uint32_t Bs[64][65];  // [n][k]

    const int tid = threadIdx.x;             // 256 threads
    const int n0 = blockIdx.x * 64;
    const int warp = tid >> 5, lane = tid & 31;
    const int wm = (warp & 3) * 16;          // 4 warps along M
    const int wn = (warp >> 2) * 32;         // 2 warps along N
    const int g = lane >> 2, tg = lane & 3;

    float acc[4][4];
#pragma unroll
    for (int i = 0; i < 4; i++)
#pragma unroll
        for (int j = 0; j < 4; j++) acc[i][j] = 0.f;

    for (int k0 = 0; k0 < K; k0 += 64) {
#pragma unroll
        for (int i = 0; i < 16; i++) {
            int idx = tid + i * 256;
            int m = idx >> 6, k = idx & 63;
            As[m][k] = f2tf32(X[(size_t)m * K + k0 + k]);
        }
#pragma unroll
        for (int i = 0; i < 16; i++) {
            int idx = tid + i * 256;
            int n = idx >> 6, k = idx & 63;
            int gn = n0 + n;
            float v = (gn < N) ? W[(size_t)gn * K + k0 + k] : 0.f;
            Bs[n][k] = f2tf32(v);
        }
        __syncthreads();

#pragma unroll
        for (int ks = 0; ks < 8; ks++) {
            uint32_t a0 = As[wm + g][ks * 8 + tg];
            uint32_t a1 = As[wm + g + 8][ks * 8 + tg];
            uint32_t a2 = As[wm + g][ks * 8 + tg + 4];
            uint32_t a3 = As[wm + g + 8][ks * 8 + tg + 4];
#pragma unroll
            for (int nt = 0; nt < 4; nt++) {
                uint32_t b0 = Bs[wn + nt * 8 + g][ks * 8 + tg];
                uint32_t b1 = Bs[wn + nt * 8 + g][ks * 8 + tg + 4];
                mma_tf32(acc[nt], a0, a1, a2, a3, b0, b1);
            }
        }
        __syncthreads();
    }

#pragma unroll
    for (int nt = 0; nt < 4; nt++) {
        int col = wn + nt * 8 + 2 * tg;
        int row0 = wm + g;
        int row1 = row0 + 8;
#pragma unroll
        for (int cc = 0; cc < 2; cc++) {
            int gn = n0 + col + cc;
            if (gn < N) {
                float bv = bias ? bias[gn] : 0.f;
                float v0 = acc[nt][cc] + bv;
                float v1 = acc[nt][2 + cc] + bv;
                if (ACT_TANH) { v0 = tanhf(v0); v1 = tanhf(v1); }
                C[(size_t)row0 * N + gn] = v0;
                C[(size_t)row1 * N + gn] = v1;
            }
        }
    }
}

// ---------------- precise 64xN GEMM (3xTF32): ~fp32 accuracy ----------------
// TILE_K = 32. TRANS=false: W is [N,K] (C = X @ W^T); TRANS=true: W is [K,N].
// Dual-problem trick via blockIdx.y.
template <bool TRANS>
__global__ __launch_bounds__(256) void gemm64p_kernel(
        const float* __restrict__ X,
        const float* __restrict__ W,
        const float* __restrict__ bias,
        float* __restrict__ C, int N, int K,
        const float* __restrict__ X2,
        const float* __restrict__ W2,
        const float* __restrict__ bias2,
        float* __restrict__ C2, int N2, int K2) {
    if (blockIdx.y == 1) { X = X2; W = W2; bias = bias2; C = C2; N = N2; K = K2; }

    __shared__ uint32_t Ah[64][33], Al[64][33];
    __shared__ uint32_t Bh[64][33], Bl[64][33];

    const int tid = threadIdx.x;             // 256 threads
    const int n0 = blockIdx.x * 64;
    const int warp = tid >> 5, lane = tid & 31;
    const int wm = (warp & 3) * 16;
    const int wn = (warp >> 2) * 32;
    const int g = lane >> 2, tg = lane & 3;

    float acc[4][4];
#pragma unroll
    for (int i = 0; i < 4; i++)
#pragma unroll
        for (int j = 0; j < 4; j++) acc[i][j] = 0.f;

    for (int k0 = 0; k0 < K; k0 += 32) {
        // A: 64x32 elements, 8 per thread
#pragma unroll
        for (int i = 0; i < 8; i++) {
            int idx = tid + i * 256;
            int m = idx >> 5, k = idx & 31;
            uint32_t hi, lo;
            split_tf32(X[(size_t)m * K + k0 + k], hi, lo);
            Ah[m][k] = hi; Al[m][k] = lo;
        }
        // B: 64x32 elements
        if (!TRANS) {
#pragma unroll
            for (int i = 0; i < 8; i++) {
                int idx = tid + i * 256;
                int n = idx >> 5, k = idx & 31;
                int gn = n0 + n;
                float v = (gn < N) ? W[(size_t)gn * K + k0 + k] : 0.f;
                uint32_t hi, lo;
                split_tf32(v, hi, lo);
                Bh[n][k] = hi; Bl[n][k] = lo;
            }
        } else {
#pragma unroll
            for (int i = 0; i < 8; i++) {
                int idx = tid + i * 256;
                int k = idx >> 5, n = idx & 31;   // k rows of W, n cols within tile... careful:
                // W is [K,N]; idx enumerates (k in 0..31 along K-tile) x (n in 0..31)? need 64 n.
                // Re-derive: need Bs[n][k] for n in 0..63, k in 0..31 -> 2048 elems.
                int nn = idx >> 5;     // 0..63
                int kk = idx & 31;     // 0..31
                int gn = n0 + nn;
                float v = (gn < N) ? W[(size_t)(k0 + kk) * N + gn] : 0.f;
                uint32_t hi, lo;
                split_tf32(v, hi, lo);
                Bh[nn][kk] = hi; Bl[nn][kk] = lo;
                (void)k; (void)n;
            }
        }
        __syncthreads();

#pragma unroll
        for (int ks = 0; ks < 4; ks++) {
            uint32_t ah0 = Ah[wm + g][ks * 8 + tg];
            uint32_t ah1 = Ah[wm + g + 8][ks * 8 + tg];
            uint32_t ah2 = Ah[wm + g][ks * 8 + tg + 4];
            uint32_t ah3 = Ah[wm + g + 8][ks * 8 + tg + 4];
            uint32_t al0 = Al[wm + g][ks * 8 + tg];
            uint32_t al1 = Al[wm + g + 8][ks * 8 + tg];
            uint32_t al2 = Al[wm + g][ks * 8 + tg + 4];
            uint32_t al3 = Al[wm + g + 8][ks * 8 + tg + 4];
#pragma unroll
            for (int nt = 0; nt < 4; nt++) {
                uint32_t bh0 = Bh[wn + nt * 8 + g][ks * 8 + tg];
                uint32_t bh1 = Bh[wn + nt * 8 + g][ks * 8 + tg + 4];
                uint32_t bl0 = Bl[wn + nt * 8 + g][ks * 8 + tg];
                uint32_t bl1 = Bl[wn + nt * 8 + g][ks * 8 + tg + 4];
                mma_tf32(acc[nt], ah0, ah1, ah2, ah3, bl0, bl1);
                mma_tf32(acc[nt], al0, al1, al2, al3, bh0, bh1);
                mma_tf32(acc[nt], ah0, ah1, ah2, ah3, bh0, bh1);
            }
        }
        __syncthreads();
    }

#pragma unroll
    for (int nt = 0; nt < 4; nt++) {
        int col = wn + nt * 8 + 2 * tg;
        int row0 = wm + g;
        int row1 = row0 + 8;
#pragma unroll
        for (int cc = 0; cc < 2; cc++) {
            int gn = n0 + col + cc;
            if (gn < N) {
                float bv = bias ? bias[gn] : 0.f;
                C[(size_t)row0 * N + gn] = acc[nt][cc] + bv;
                C[(size_t)row1 * N + gn] = acc[nt][2 + cc] + bv;
            }
        }
    }
}

// ---------------- GRU gates ----------------
__global__ __launch_bounds__(256) void gru_gates_kernel(
        const float* __restrict__ hprev, float* __restrict__ hnew) {
    int idx = blockIdx.x * blockDim.x + threadIdx.x;  // B*H
    int b = idx >> 10;
    int h = idx & 1023;
    size_t base = (size_t)b * 3 * HH;
    float ir = g_gi[base + h];
    float iz = g_gi[base + HH + h];
    float in_ = g_gi[base + 2 * HH + h];
    float hr = g_gh[base + h];
    float hz = g_gh[base + HH + h];
    float hn = g_gh[base + 2 * HH + h];
    float r = 1.f / (1.f + __expf(-(ir + hr)));
    float z = 1.f / (1.f + __expf(-(iz + hz)));
    float n = tanhf(in_ + r * hn);
    hnew[idx] = (1.f - z) * n + z * hprev[idx];
}

// ---------------- new_hidden = stack(h0,h1) + embedded ----------------
__global__ __launch_bounds__(256) void new_hidden_kernel(float* __restrict__ hid_out) {
    int idx = blockIdx.x * blockDim.x + threadIdx.x;  // B*H
    int b = idx >> 10;
    int h = idx & 1023;
    float emb = g_x[b * 2 * HH + h];
    hid_out[idx] = g_h0[idx] + emb;
    hid_out[BB * HH + idx] = g_h1[idx] + emb;
}

// ---------------- attention: per-segment online softmax + context ----------------
// grid (8, B), 256 threads; each warp owns one 32-step T segment.
__global__ __launch_bounds__(256) void attn_partial_kernel(const float* __restrict__ enc) {
    int b = blockIdx.y;
    int warp = threadIdx.x >> 5, lane = threadIdx.x & 31;
    int seg = blockIdx.x * 8 + warp;  // 0..63

    float4 uu[8];
#pragma unroll
    for (int i = 0; i < 8; i++)
        uu[i] = *(const float4*)&g_u[b * HH + i * 128 + lane * 4];

    float4 cc[8];
#pragma unroll
    for (int i = 0; i < 8; i++) cc[i] = make_float4(0.f, 0.f, 0.f, 0.f);

    float m = -1e30f, l = 0.f;
    int t0 = seg * 32;
    for (int tt = 0; tt < 32; tt++) {
        int t = t0 + tt;
        const float* ep = enc + ((size_t)t * BB + b) * HH;
        float4 e[8];
#pragma unroll
        for (int i = 0; i < 8; i++)
            e[i] = *(const float4*)&ep[i * 128 + lane * 4];
        float d = 0.f;
#pragma unroll
        for (int i = 0; i < 8; i++) {
            d += e[i].x * uu[i].x + e[i].y * uu[i].y +
                 e[i].z * uu[i].z + e[i].w * uu[i].w;
        }
#pragma unroll
        for (int o = 16; o; o >>= 1) d += __shfl_xor_sync(0xffffffffu, d, o);

        if (lane == 0) g_scores[b * TT + t] = d;

        float mn = fmaxf(m, d);
        float corr = __expf(m - mn);
        float p = __expf(d - mn);
        l = l * corr + p;
        m = mn;
#pragma unroll
        for (int i = 0; i < 8; i++) {
            cc[i].x = cc[i].x * corr + p * e[i].x;
            cc[i].y = cc[i].y * corr + p * e[i].y;
            cc[i].z = cc[i].z * corr + p * e[i].z;
            cc[i].w = cc[i].w * corr + p * e[i].w;
        }
    }
    float* cp = &g_ctxpart[((size_t)b * 64 + seg) * HH];
#pragma unroll
    for (int i = 0; i < 8; i++)
        *(float4*)&cp[i * 128 + lane * 4] = cc[i];
    if (lane == 0) {
        g_mpart[b * 64 + seg] = m;
        g_lpart[b * 64 + seg] = l;
    }
}

// ---------------- combine partials -> context; build y ----------------
__global__ __launch_bounds__(256) void attn_combine_kernel(float* __restrict__ ctx_out) {
    int b = blockIdx.x;
    int tid = threadIdx.x;  // 256
    __shared__ float sm[64], sl[64], sw[64];
    __shared__ float sML[2];
    if (tid < 64) {
        sm[tid] = g_mpart[b * 64 + tid];
        sl[tid] = g_lpart[b * 64 + tid];
    }
    __syncthreads();
    if (tid == 0) {
        float M = -1e30f;
        for (int s = 0; s < 64; s++) M = fmaxf(M, sm[s]);
        float L = 0.f;
        for (int s = 0; s < 64; s++) L += sl[s] * __expf(sm[s] - M);
        sML[0] = M; sML[1] = L;
        g_M[b] = M; g_L[b] = L;
    }
    __syncthreads();
    if (tid < 64) sw[tid] = __expf(sm[tid] - sML[0]) / sML[1];
    __syncthreads();

    int h = tid * 4;
    float4 a = make_float4(0.f, 0.f, 0.f, 0.f);
    for (int s = 0; s < 64; s++) {
        float4 v = *(const float4*)&g_ctxpart[((size_t)b * 64 + s) * HH + h];
        float w = sw[s];
        a.x += w * v.x; a.y += w * v.y; a.z += w * v.z; a.w += w * v.w;
    }
    *(float4*)&ctx_out[b * HH + h] = a;
    *(float4*)&g_y[b * 2 * HH + HH + h] = a;                       // second half of y
    float4 o = *(const float4*)&g_h1[b * HH + h];
    *(float4*)&g_y[b * 2 * HH + h] = o;                            // first half of y
}

// ---------------- attn probs to output ----------------
__global__ __launch_bounds__(256) void attn_write_kernel(float* __restrict__ attn_out) {
    int idx = blockIdx.x * blockDim.x + threadIdx.x;  // B*T
    int b = idx >> 11;
    attn_out[idx] = __expf(g_scores[idx] - g_M[b]) / g_L[b];
}

// ---------------- log-sum-exp over V per batch ----------------
__global__ __launch_bounds__(256) void lse_kernel() {
    int b = blockIdx.x;
    int tid = threadIdx.x;  // 256
    float m = -1e30f, l = 0.f;
    const float* row = &g_logits[(size_t)b * VV];
    for (int v = tid; v < VV; v += 256) {
        float x = row[v];
        if (x > m) {
            l = l * __expf(m - x) + 1.f;
            m = x;
        } else {
            l += __expf(x - m);
        }
    }
#pragma unroll
    for (int o = 16; o; o >>= 1) {
        float mo = __shfl_xor_sync(0xffffffffu, m, o);
        float lo = __shfl_xor_sync(0xffffffffu, l, o);
        float M = fmaxf(m, mo);
        l = l * __expf(m - M) + lo * __expf(mo - M);
        m = M;
    }
    __shared__ float wm[8], wl[8];
    if ((tid & 31) == 0) { wm[tid >> 5] = m; wl[tid >> 5] = l; }
    __syncthreads();
    if (tid == 0) {
        float M = -1e30f;
        for (int w = 0; w < 8; w++) M = fmaxf(M, wm[w]);
        float L = 0.f;
        for (int w = 0; w < 8; w++) L += wl[w] * __expf(wm[w] - M);
        g_lse[b] = M + logf(L);
    }
}

// ---------------- out = logits - lse ----------------
__global__ __launch_bounds__(256) void out_write_kernel(float* __restrict__ out) {
    int idx = blockIdx.x * blockDim.x + threadIdx.x;
    if (idx >= BB * VV) return;
    int b = idx / VV;
    out[idx] = g_logits[idx] - g_lse[b];
}

// ---------------- launch ----------------
extern "C" void kernel_launch(void* const* d_in, const int* in_sizes, int n_in,
                              void* d_out, int out_size) {
    const int*   inputs  = (const int*)d_in[0];
    const float* hidden  = (const float*)d_in[1];   // [2,B,H]
    const float* context = (const float*)d_in[2];   // [B,H]
    const float* enc     = (const float*)d_in[3];   // [T,B,H]
    const float* E       = (const float*)d_in[4];   // [V,H]
    const float* W_ih0   = (const float*)d_in[5];   // [3H,2H]
    const float* W_hh0   = (const float*)d_in[6];   // [3H,H]
    const float* b_ih0   = (const float*)d_in[7];
    const float* b_hh0   = (const float*)d_in[8];
    const float* W_ih1   = (const float*)d_in[9];   // [3H,H]
    const float* W_hh1   = (const float*)d_in[10];  // [3H,H]
    const float* b_ih1   = (const float*)d_in[11];
    const float* b_hh1   = (const float*)d_in[12];
    const float* Wa      = (const float*)d_in[13];  // [H,H]
    // d_in[14] = ba: softmax is invariant to the per-batch constant it adds -> unused
    const float* Wo      = (const float*)d_in[15];  // [V,2H]
    const float* bo      = (const float*)d_in[16];

    float* out0     = (float*)d_out;                       // [B,V]
    float* hid_out  = out0 + (size_t)BB * VV;              // [2,B,H]
    float* ctx_out  = hid_out + 2 * BB * HH;               // [B,H]
    float* attn_out = ctx_out + BB * HH;                   // [B,1,T]

    void *p_x, *p_gi, *p_gh, *p_h0, *p_h1, *p_u, *p_y, *p_logits;
    cudaGetSymbolAddress(&p_x, g_x);
    cudaGetSymbolAddress(&p_gi, g_gi);
    cudaGetSymbolAddress(&p_gh, g_gh);
    cudaGetSymbolAddress(&p_h0, g_h0);
    cudaGetSymbolAddress(&p_h1, g_h1);
    cudaGetSymbolAddress(&p_u, g_u);
    cudaGetSymbolAddress(&p_y, g_y);
    cudaGetSymbolAddress(&p_logits, g_logits);
    float* xx = (float*)p_x;
    float* gi = (float*)p_gi;
    float* gh = (float*)p_gh;
    float* h0 = (float*)p_h0;
    float* h1 = (float*)p_h1;
    float* uu = (float*)p_u;
    float* yy = (float*)p_y;
    float* lg = (float*)p_logits;

    // 1) x = concat(E[inputs], context)
    build_x_kernel<<<(BB * 2 * HH) / 256, 256>>>(inputs, E, context);

    // 2) GRU layer 0 (precise 3xTF32)
    gemm64p_kernel<false><<<dim3(48, 2), 256>>>(
        xx, W_ih0, b_ih0, gi, 3 * HH, 2 * HH,
        hidden, W_hh0, b_hh0, gh, 3 * HH, HH);
    gru_gates_kernel<<<(BB * HH) / 256, 256>>>(hidden, h0);

    // 3) GRU layer 1 (precise 3xTF32)
    gemm64p_kernel<false><<<dim3(48, 2), 256>>>(
        h0, W_ih1, b_ih1, gi, 3 * HH, HH,
        hidden + BB * HH, W_hh1, b_hh1, gh, 3 * HH, HH);
    gru_gates_kernel<<<(BB * HH) / 256, 256>>>(hidden + BB * HH, h1);

    // 4) new_hidden = stack(h0,h1) + embedded
    new_hidden_kernel<<<(BB * HH) / 256, 256>>>(hid_out);

    // 5) u = output @ Wa (precise 3xTF32; Wa is [K=H rows][N=H cols] -> TRANS)
    gemm64p_kernel<true><<<dim3(16, 1), 256>>>(
        h1, Wa, nullptr, uu, HH, HH,
        nullptr, nullptr, nullptr, nullptr, 0, 0);

    // 6) fused flash-attention pass over encoderOutput
    attn_partial_kernel<<<dim3(8, BB), 256>>>(enc);
    attn_combine_kernel<<<BB, 256>>>(ctx_out);
    attn_write_kernel<<<(BB * TT) / 256, 256>>>(attn_out);

    // 7) logits = tanh(y @ Wo^T + bo) (1xTF32, validated)
    gemm64_kernel<true><<<dim3((VV + 63) / 64, 1), 256>>>(yy, Wo, bo, lg, VV, 2 * HH);

    // 8) log_softmax
    lse_kernel<<<BB, 256>>>();
    out_write_kernel<<<(BB * VV + 255) / 256, 256>>>(out0);
}

// round 5
// speedup vs baseline: 3.1247x; 3.1247x over previous
#include <cuda_runtime.h>
#include <cstdint>
#include <cstddef>

#define HH 1024
#define VV 50257
#define BB 64
#define TT 2048

#define STAGES 4
#define STAGE_FLOATS 2304           // per-stage per-array floats (64*36 = 2304; trans B uses 32*68=2176)
#define GEMM_SMEM_BYTES (STAGES * 2 * STAGE_FLOATS * 4)   // 73728

// ---------------- scratch (device globals: no allocation) ----------------
__device__ float g_x[BB * 2 * HH];          // [B,2H] concat(embedded, context)
__device__ float g_gi[BB * 3 * HH];
__device__ float g_gh[BB * 3 * HH];
__device__ float g_h0[BB * HH];
__device__ float g_h1[BB * HH];
__device__ float g_u[BB * HH];              // output @ Wa
__device__ float g_scores[BB * TT];
__device__ float g_ctxpart[(size_t)BB * 64 * HH];   // 16.8 MB
__device__ float g_mpart[BB * 64];
__device__ float g_lpart[BB * 64];
__device__ float g_M[BB];
__device__ float g_L[BB];
__device__ float g_y[BB * 2 * HH];          // [B,2H] concat(output, context)
__device__ float g_logits[(size_t)BB * VV];
__device__ float g_lse[BB];

// ---------------- helpers ----------------
__device__ __forceinline__ uint32_t f2tf32(float f) {
    uint32_t u;
    asm("cvt.rna.tf32.f32 %0, %1;" : "=r"(u) : "f"(f));
    return u;
}

__device__ __forceinline__ void mma_tf32(float c[4], uint32_t a0, uint32_t a1,
                                         uint32_t a2, uint32_t a3,
                                         uint32_t b0, uint32_t b1) {
    asm volatile(
        "mma.sync.aligned.m16n8k8.row.col.f32.tf32.tf32.f32 "
        "{%0,%1,%2,%3}, {%4,%5,%6,%7}, {%8,%9}, {%0,%1,%2,%3};"
        : "+f"(c[0]), "+f"(c[1]), "+f"(c[2]), "+f"(c[3])
        : "r"(a0), "r"(a1), "r"(a2), "r"(a3), "r"(b0), "r"(b1));
}

__device__ __forceinline__ void cp_async16(float* dst, const float* src) {
    uint32_t s = (uint32_t)__cvta_generic_to_shared(dst);
    asm volatile("cp.async.cg.shared.global [%0], [%1], 16;" :: "r"(s), "l"(src));
}
__device__ __forceinline__ void cp_async16_z(float* dst, const float* src, bool valid) {
    uint32_t s = (uint32_t)__cvta_generic_to_shared(dst);
    int sz = valid ? 16 : 0;
    asm volatile("cp.async.cg.shared.global [%0], [%1], 16, %2;" :: "r"(s), "l"(src), "r"(sz));
}
__device__ __forceinline__ void cp_commit() { asm volatile("cp.async.commit_group;"); }
template <int N>
__device__ __forceinline__ void cp_wait() { asm volatile("cp.async.wait_group %0;" :: "n"(N)); }

// ---------------- K1: x = concat(E[inputs], context) ----------------
__global__ __launch_bounds__(256) void build_x_kernel(
        const int* __restrict__ inputs,
        const float* __restrict__ E,
        const float* __restrict__ context) {
    int idx = blockIdx.x * blockDim.x + threadIdx.x;  // B*2H = 131072
    int b = idx >> 11;
    int j = idx & 2047;
    float v;
    if (j < HH) v = E[(size_t)inputs[b] * HH + j];
    else        v = context[b * HH + (j - HH)];
    g_x[idx] = v;
}

// ---------------- pipelined 64xN GEMM ----------------
// C[64,N] = X[64,K] @ op(W)^T + bias. TILE_N=64, TILE_K=32, 4-stage cp.async.
// TRANS=false: W [N,K] row-major. TRANS=true: W [K,N] row-major.
// PRECISE: 3xTF32 split product (~fp32). Dual problem via blockIdx.y.
template <bool PRECISE, bool TRANS, bool ACT_TANH>
__global__ __launch_bounds__(256) void gemm_pipe_kernel(
        const float* __restrict__ X, const float* __restrict__ W,
        const float* __restrict__ bias, float* __restrict__ C, int N, int K,
        const float* __restrict__ X2, const float* __restrict__ W2,
        const float* __restrict__ bias2, float* __restrict__ C2, int N2, int K2) {
    if (blockIdx.y == 1) { X = X2; W = W2; bias = bias2; C = C2; N = N2; K = K2; }

    extern __shared__ float smem[];
    float* Abase = smem;                       // [STAGES][64][36]
    float* Bbase = smem + STAGES * STAGE_FLOATS;

    const int tid = threadIdx.x;               // 256
    const int n0 = blockIdx.x * 64;
    const int warp = tid >> 5, lane = tid & 31;
    const int wm = (warp & 3) * 16;
    const int wn = (warp >> 2) * 32;
    const int g = lane >> 2, tg = lane & 3;

    const int nk = K >> 5;

    auto load_stage = [&](int s, int kt) {
        int k0 = kt << 5;
        float* As = Abase + s * STAGE_FLOATS;
        float* Bs = Bbase + s * STAGE_FLOATS;
#pragma unroll
        for (int i = 0; i < 2; i++) {           // A: 512 x 16B chunks
            int c = tid + i * 256;
            int m = c >> 3, cc = c & 7;
            cp_async16(As + m * 36 + cc * 4, X + (size_t)m * K + k0 + cc * 4);
        }
        if (!TRANS) {
#pragma unroll
            for (int i = 0; i < 2; i++) {       // B: [n][k] rows
                int c = tid + i * 256;
                int n = c >> 3, cc = c & 7;
                int gn = n0 + n;
                cp_async16_z(Bs + n * 36 + cc * 4, W + (size_t)gn * K + k0 + cc * 4, gn < N);
            }
        } else {
#pragma unroll
            for (int i = 0; i < 2; i++) {       // B: [k][n] rows (W row-major [K,N])
                int c = tid + i * 256;
                int k = c >> 4, cc = c & 15;
                int gn = n0 + cc * 4;
                cp_async16_z(Bs + k * 68 + cc * 4, W + (size_t)(k0 + k) * N + gn, gn < N);
            }
        }
        cp_commit();
    };

    float acc[4][4];
#pragma unroll
    for (int i = 0; i < 4; i++)
#pragma unroll
        for (int j = 0; j < 4; j++) acc[i][j] = 0.f;

    for (int s = 0; s < STAGES - 1; s++) load_stage(s, s);

    for (int kt = 0; kt < nk; kt++) {
        cp_wait<STAGES - 2>();
        __syncthreads();
        const float* As = Abase + (kt & (STAGES - 1)) * STAGE_FLOATS;
        const float* Bs = Bbase + (kt & (STAGES - 1)) * STAGE_FLOATS;

#pragma unroll
        for (int ks = 0; ks < 4; ks++) {
            float af[4];
            af[0] = As[(wm + g) * 36 + ks * 8 + tg];
            af[1] = As[(wm + g + 8) * 36 + ks * 8 + tg];
            af[2] = As[(wm + g) * 36 + ks * 8 + tg + 4];
            af[3] = As[(wm + g + 8) * 36 + ks * 8 + tg + 4];
            uint32_t ah[4], al[4];
#pragma unroll
            for (int i = 0; i < 4; i++) {
                ah[i] = f2tf32(af[i]);
                if (PRECISE) al[i] = f2tf32(af[i] - __uint_as_float(ah[i]));
            }
#pragma unroll
            for (int nt = 0; nt < 4; nt++) {
                float bf0, bf1;
                if (!TRANS) {
                    bf0 = Bs[(wn + nt * 8 + g) * 36 + ks * 8 + tg];
                    bf1 = Bs[(wn + nt * 8 + g) * 36 + ks * 8 + tg + 4];
                } else {
                    bf0 = Bs[(ks * 8 + tg) * 68 + wn + nt * 8 + g];
                    bf1 = Bs[(ks * 8 + tg + 4) * 68 + wn + nt * 8 + g];
                }
                uint32_t bh0 = f2tf32(bf0), bh1 = f2tf32(bf1);
                if (PRECISE) {
                    uint32_t bl0 = f2tf32(bf0 - __uint_as_float(bh0));
                    uint32_t bl1 = f2tf32(bf1 - __uint_as_float(bh1));
                    mma_tf32(acc[nt], ah[0], ah[1], ah[2], ah[3], bl0, bl1);
                    mma_tf32(acc[nt], al[0], al[1], al[2], al[3], bh0, bh1);
                }
                mma_tf32(acc[nt], ah[0], ah[1], ah[2], ah[3], bh0, bh1);
            }
        }
        __syncthreads();
        if (kt + STAGES - 1 < nk) load_stage((kt + STAGES - 1) & (STAGES - 1), kt + STAGES - 1);
        else cp_commit();   // keep group accounting uniform
    }

#pragma unroll
    for (int nt = 0; nt < 4; nt++) {
        int col = wn + nt * 8 + 2 * tg;
        int row0 = wm + g;
        int row1 = row0 + 8;
#pragma unroll
        for (int cc = 0; cc < 2; cc++) {
            int gn = n0 + col + cc;
            if (gn < N) {
                float bv = bias ? bias[gn] : 0.f;
                float v0 = acc[nt][cc] + bv;
                float v1 = acc[nt][2 + cc] + bv;
                if (ACT_TANH) { v0 = tanhf(v0); v1 = tanhf(v1); }
                C[(size_t)row0 * N + gn] = v0;
                C[(size_t)row1 * N + gn] = v1;
            }
        }
    }
}

// ---------------- GRU gates ----------------
__global__ __launch_bounds__(256) void gru_gates_kernel(
        const float* __restrict__ hprev, float* __restrict__ hnew) {
    int idx = blockIdx.x * blockDim.x + threadIdx.x;  // B*H
    int b = idx >> 10;
    int h = idx & 1023;
    size_t base = (size_t)b * 3 * HH;
    float ir = g_gi[base + h];
    float iz = g_gi[base + HH + h];
    float in_ = g_gi[base + 2 * HH + h];
    float hr = g_gh[base + h];
    float hz = g_gh[base + HH + h];
    float hn = g_gh[base + 2 * HH + h];
    float r = 1.f / (1.f + __expf(-(ir + hr)));
    float z = 1.f / (1.f + __expf(-(iz + hz)));
    float n = tanhf(in_ + r * hn);
    hnew[idx] = (1.f - z) * n + z * hprev[idx];
}

// ---------------- new_hidden = stack(h0,h1) + embedded ----------------
__global__ __launch_bounds__(256) void new_hidden_kernel(float* __restrict__ hid_out) {
    int idx = blockIdx.x * blockDim.x + threadIdx.x;  // B*H
    int b = idx >> 10;
    int h = idx & 1023;
    float emb = g_x[b * 2 * HH + h];
    hid_out[idx] = g_h0[idx] + emb;
    hid_out[BB * HH + idx] = g_h1[idx] + emb;
}

// ---------------- attention: per-segment online softmax + context ----------------
// grid (16, B), 128 threads; each warp owns one 32-step T segment.
// Software-pipelined: next timestep's enc row prefetched into registers.
__global__ __launch_bounds__(128) void attn_partial_kernel(const float* __restrict__ enc) {
    const int b = blockIdx.y;
    const int warp = threadIdx.x >> 5, lane = threadIdx.x & 31;
    const int seg = blockIdx.x * 4 + warp;  // 0..63
    const size_t tstride = (size_t)BB * HH;

    float4 uu[8];
#pragma unroll
    for (int i = 0; i < 8; i++)
        uu[i] = *(const float4*)&g_u[b * HH + i * 128 + lane * 4];

    float4 cc[8];
#pragma unroll
    for (int i = 0; i < 8; i++) cc[i] = make_float4(0.f, 0.f, 0.f, 0.f);

    float m = -1e30f, l = 0.f;
    const int t0 = seg * 32;
    const float* ep = enc + ((size_t)t0 * BB + b) * HH;

    float4 eA[8], eB[8];
#pragma unroll
    for (int i = 0; i < 8; i++)
        eA[i] = *(const float4*)&ep[i * 128 + lane * 4];

    auto process = [&](const float4 (&e)[8], int t) {
        float d = 0.f;
#pragma unroll
        for (int i = 0; i < 8; i++) {
            d += e[i].x * uu[i].x + e[i].y * uu[i].y +
                 e[i].z * uu[i].z + e[i].w * uu[i].w;
        }
#pragma unroll
        for (int o = 16; o; o >>= 1) d += __shfl_xor_sync(0xffffffffu, d, o);
        if (lane == 0) g_scores[b * TT + t] = d;
        float mn = fmaxf(m, d);
        float corr = __expf(m - mn);
        float p = __expf(d - mn);
        l = l * corr + p;
        m = mn;
#pragma unroll
        for (int i = 0; i < 8; i++) {
            cc[i].x = cc[i].x * corr + p * e[i].x;
            cc[i].y = cc[i].y * corr + p * e[i].y;
            cc[i].z = cc[i].z * corr + p * e[i].z;
            cc[i].w = cc[i].w * corr + p * e[i].w;
        }
    };

    for (int tt = 0; tt < 32; tt += 2) {
        const float* ep1 = ep + tstride;
#pragma unroll
        for (int i = 0; i < 8; i++)
            eB[i] = *(const float4*)&ep1[i * 128 + lane * 4];
        process(eA, t0 + tt);
        const float* ep2 = ep + 2 * tstride;
        if (tt + 2 < 32) {
#pragma unroll
            for (int i = 0; i < 8; i++)
                eA[i] = *(const float4*)&ep2[i * 128 + lane * 4];
        }
        process(eB, t0 + tt + 1);
        ep = ep2;
    }

    float* cp = &g_ctxpart[((size_t)b * 64 + seg) * HH];
#pragma unroll
    for (int i = 0; i < 8; i++)
        *(float4*)&cp[i * 128 + lane * 4] = cc[i];
    if (lane == 0) {
        g_mpart[b * 64 + seg] = m;
        g_lpart[b * 64 + seg] = l;
    }
}

// ---------------- combine partials -> context; build y ----------------
__global__ __launch_bounds__(256) void attn_combine_kernel(float* __restrict__ ctx_out) {
    int b = blockIdx.x;
    int tid = threadIdx.x;  // 256
    __shared__ float sm[64], sl[64], sw[64];
    __shared__ float sML[2];
    if (tid < 64) {
        sm[tid] = g_mpart[b * 64 + tid];
        sl[tid] = g_lpart[b * 64 + tid];
    }
    __syncthreads();
    if (tid == 0) {
        float M = -1e30f;
        for (int s = 0; s < 64; s++) M = fmaxf(M, sm[s]);
        float L = 0.f;
        for (int s = 0; s < 64; s++) L += sl[s] * __expf(sm[s] - M);
        sML[0] = M; sML[1] = L;
        g_M[b] = M; g_L[b] = L;
    }
    __syncthreads();
    if (tid < 64) sw[tid] = __expf(sm[tid] - sML[0]) / sML[1];
    __syncthreads();

    int h = tid * 4;
    float4 a = make_float4(0.f, 0.f, 0.f, 0.f);
    for (int s = 0; s < 64; s++) {
        float4 v = *(const float4*)&g_ctxpart[((size_t)b * 64 + s) * HH + h];
        float w = sw[s];
        a.x += w * v.x; a.y += w * v.y; a.z += w * v.z; a.w += w * v.w;
    }
    *(float4*)&ctx_out[b * HH + h] = a;
    *(float4*)&g_y[b * 2 * HH + HH + h] = a;                       // second half of y
    float4 o = *(const float4*)&g_h1[b * HH + h];
    *(float4*)&g_y[b * 2 * HH + h] = o;                            // first half of y
}

// ---------------- attn probs to output ----------------
__global__ __launch_bounds__(256) void attn_write_kernel(float* __restrict__ attn_out) {
    int idx = blockIdx.x * blockDim.x + threadIdx.x;  // B*T
    int b = idx >> 11;
    attn_out[idx] = __expf(g_scores[idx] - g_M[b]) / g_L[b];
}

// ---------------- log-sum-exp over V per batch ----------------
__global__ __launch_bounds__(256) void lse_kernel() {
    int b = blockIdx.x;
    int tid = threadIdx.x;  // 256
    float m = -1e30f, l = 0.f;
    const float* row = &g_logits[(size_t)b * VV];
    for (int v = tid; v < VV; v += 256) {
        float x = row[v];
        if (x > m) {
            l = l * __expf(m - x) + 1.f;
            m = x;
        } else {
            l += __expf(x - m);
        }
    }
#pragma unroll
    for (int o = 16; o; o >>= 1) {
        float mo = __shfl_xor_sync(0xffffffffu, m, o);
        float lo = __shfl_xor_sync(0xffffffffu, l, o);
        float M = fmaxf(m, mo);
        l = l * __expf(m - M) + lo * __expf(mo - M);
        m = M;
    }
    __shared__ float wm[8], wl[8];
    if ((tid & 31) == 0) { wm[tid >> 5] = m; wl[tid >> 5] = l; }
    __syncthreads();
    if (tid == 0) {
        float M = -1e30f;
        for (int w = 0; w < 8; w++) M = fmaxf(M, wm[w]);
        float L = 0.f;
        for (int w = 0; w < 8; w++) L += wl[w] * __expf(wm[w] - M);
        g_lse[b] = M + logf(L);
    }
}

// ---------------- out = logits - lse ----------------
__global__ __launch_bounds__(256) void out_write_kernel(float* __restrict__ out) {
    int idx = blockIdx.x * blockDim.x + threadIdx.x;
    if (idx >= BB * VV) return;
    int b = idx / VV;
    out[idx] = g_logits[idx] - g_lse[b];
}

// ---------------- launch ----------------
extern "C" void kernel_launch(void* const* d_in, const int* in_sizes, int n_in,
                              void* d_out, int out_size) {
    const int*   inputs  = (const int*)d_in[0];
    const float* hidden  = (const float*)d_in[1];   // [2,B,H]
    const float* context = (const float*)d_in[2];   // [B,H]
    const float* enc     = (const float*)d_in[3];   // [T,B,H]
    const float* E       = (const float*)d_in[4];   // [V,H]
    const float* W_ih0   = (const float*)d_in[5];   // [3H,2H]
    const float* W_hh0   = (const float*)d_in[6];   // [3H,H]
    const float* b_ih0   = (const float*)d_in[7];
    const float* b_hh0   = (const float*)d_in[8];
    const float* W_ih1   = (const float*)d_in[9];   // [3H,H]
    const float* W_hh1   = (const float*)d_in[10];  // [3H,H]
    const float* b_ih1   = (const float*)d_in[11];
    const float* b_hh1   = (const float*)d_in[12];
    const float* Wa      = (const float*)d_in[13];  // [H,H]
    // d_in[14] = ba: softmax is invariant to the per-batch constant it adds -> unused
    const float* Wo      = (const float*)d_in[15];  // [V,2H]
    const float* bo      = (const float*)d_in[16];

    float* out0     = (float*)d_out;                       // [B,V]
    float* hid_out  = out0 + (size_t)BB * VV;              // [2,B,H]
    float* ctx_out  = hid_out + 2 * BB * HH;               // [B,H]
    float* attn_out = ctx_out + BB * HH;                   // [B,1,T]

    void *p_x, *p_gi, *p_gh, *p_h0, *p_h1, *p_u, *p_y, *p_logits;
    cudaGetSymbolAddress(&p_x, g_x);
    cudaGetSymbolAddress(&p_gi, g_gi);
    cudaGetSymbolAddress(&p_gh, g_gh);
    cudaGetSymbolAddress(&p_h0, g_h0);
    cudaGetSymbolAddress(&p_h1, g_h1);
    cudaGetSymbolAddress(&p_u, g_u);
    cudaGetSymbolAddress(&p_y, g_y);
    cudaGetSymbolAddress(&p_logits, g_logits);
    float* xx = (float*)p_x;
    float* gi = (float*)p_gi;
    float* gh = (float*)p_gh;
    float* h0 = (float*)p_h0;
    float* h1 = (float*)p_h1;
    float* uu = (float*)p_u;
    float* yy = (float*)p_y;
    float* lg = (float*)p_logits;

    // opt-in to 72KB dynamic smem (idempotent; not stream-ordered; capture-safe)
    static bool attr_done = false;
    if (!attr_done) {
        cudaFuncSetAttribute(gemm_pipe_kernel<true, false, false>,
                             cudaFuncAttributeMaxDynamicSharedMemorySize, GEMM_SMEM_BYTES);
        cudaFuncSetAttribute(gemm_pipe_kernel<true, true, false>,
                             cudaFuncAttributeMaxDynamicSharedMemorySize, GEMM_SMEM_BYTES);
        cudaFuncSetAttribute(gemm_pipe_kernel<false, false, true>,
                             cudaFuncAttributeMaxDynamicSharedMemorySize, GEMM_SMEM_BYTES);
        attr_done = true;
    }

    // 1) x = concat(E[inputs], context)
    build_x_kernel<<<(BB * 2 * HH) / 256, 256>>>(inputs, E, context);

    // 2) GRU layer 0 (precise 3xTF32, pipelined)
    gemm_pipe_kernel<true, false, false><<<dim3(48, 2), 256, GEMM_SMEM_BYTES>>>(
        xx, W_ih0, b_ih0, gi, 3 * HH, 2 * HH,
        hidden, W_hh0, b_hh0, gh, 3 * HH, HH);
    gru_gates_kernel<<<(BB * HH) / 256, 256>>>(hidden, h0);

    // 3) GRU layer 1 (precise 3xTF32, pipelined)
    gemm_pipe_kernel<true, false, false><<<dim3(48, 2), 256, GEMM_SMEM_BYTES>>>(
        h0, W_ih1, b_ih1, gi, 3 * HH, HH,
        hidden + BB * HH, W_hh1, b_hh1, gh, 3 * HH, HH);
    gru_gates_kernel<<<(BB * HH) / 256, 256>>>(hidden + BB * HH, h1);

    // 4) new_hidden = stack(h0,h1) + embedded
    new_hidden_kernel<<<(BB * HH) / 256, 256>>>(hid_out);

    // 5) u = output @ Wa (precise, Wa is [K=H][N=H] -> TRANS)
    gemm_pipe_kernel<true, true, false><<<dim3(16, 1), 256, GEMM_SMEM_BYTES>>>(
        h1, Wa, nullptr, uu, HH, HH,
        nullptr, nullptr, nullptr, nullptr, 0, 0);

    // 6) fused flash-attention pass over encoderOutput
    attn_partial_kernel<<<dim3(16, BB), 128>>>(enc);
    attn_combine_kernel<<<BB, 256>>>(ctx_out);
    attn_write_kernel<<<(BB * TT) / 256, 256>>>(attn_out);

    // 7) logits = tanh(y @ Wo^T + bo) (1xTF32, validated, pipelined)
    gemm_pipe_kernel<false, false, true><<<dim3((VV + 63) / 64, 1), 256, GEMM_SMEM_BYTES>>>(
        yy, Wo, bo, lg, VV, 2 * HH,
        nullptr, nullptr, nullptr, nullptr, 0, 0);

    // 8) log_softmax
    lse_kernel<<<BB, 256>>>();
    out_write_kernel<<<(BB * VV + 255) / 256, 256>>>(out0);
}

// round 7
// speedup vs baseline: 3.7490x; 1.1998x over previous
#include <cuda_runtime.h>
#include <cstdint>
#include <cstddef>

#define HH 1024
#define VV 50257
#define BB 64
#define TT 2048

#define STAGES 4
#define STAGE_FLOATS 2304                    // A: 64*36; B: max(64*36, 32*68)
#define GEMM_SMEM_BYTES (STAGES * 2 * STAGE_FLOATS * 4)   // 73728

#define WO_STAGES 3
#define WO_A_FLOATS 2304                     // 64*36
#define WO_B_FLOATS 4608                     // 128*36
#define WO_SMEM_BYTES (WO_STAGES * (WO_A_FLOATS + WO_B_FLOATS) * 4)  // 82944

// ---------------- scratch (device globals: no allocation) ----------------
__device__ float g_x[BB * 2 * HH];          // [B,2H] concat(embedded, context)
__device__ float g_gi[BB * 3 * HH];         // gi partial A
__device__ float g_gia[BB * 3 * HH];        // gi partial B
__device__ float g_gh[BB * 3 * HH];         // gh layer-0
__device__ float g_gh1[BB * 3 * HH];        // gh layer-1 (computed early)
__device__ float g_h0[BB * HH];
__device__ float g_h1[BB * HH];
__device__ float g_up[4 * BB * HH];         // u split-K partials
__device__ float g_scores[BB * TT];
__device__ float g_ctxpart[(size_t)BB * 64 * HH];
__device__ float g_mpart[BB * 64];
__device__ float g_lpart[BB * 64];
__device__ float g_M[BB];
__device__ float g_L[BB];
__device__ float g_y[BB * 2 * HH];          // [B,2H] concat(output, context)
__device__ float g_logits[(size_t)BB * VV];
__device__ float g_lse[BB];

// ---------------- helpers ----------------
__device__ __forceinline__ uint32_t f2tf32(float f) {
    uint32_t u;
    asm("cvt.rna.tf32.f32 %0, %1;" : "=r"(u) : "f"(f));
    return u;
}

__device__ __forceinline__ void mma_tf32(float c[4], uint32_t a0, uint32_t a1,
                                         uint32_t a2, uint32_t a3,
                                         uint32_t b0, uint32_t b1) {
    asm volatile(
        "mma.sync.aligned.m16n8k8.row.col.f32.tf32.tf32.f32 "
        "{%0,%1,%2,%3}, {%4,%5,%6,%7}, {%8,%9}, {%0,%1,%2,%3};"
        : "+f"(c[0]), "+f"(c[1]), "+f"(c[2]), "+f"(c[3])
        : "r"(a0), "r"(a1), "r"(a2), "r"(a3), "r"(b0), "r"(b1));
}

__device__ __forceinline__ void cp_async16(float* dst, const float* src) {
    uint32_t s = (uint32_t)__cvta_generic_to_shared(dst);
    asm volatile("cp.async.cg.shared.global [%0], [%1], 16;" :: "r"(s), "l"(src));
}
__device__ __forceinline__ void cp_async16_z(float* dst, const float* src, bool valid) {
    uint32_t s = (uint32_t)__cvta_generic_to_shared(dst);
    int sz = valid ? 16 : 0;
    asm volatile("cp.async.cg.shared.global [%0], [%1], 16, %2;" :: "r"(s), "l"(src), "r"(sz));
}
__device__ __forceinline__ void cp_commit() { asm volatile("cp.async.commit_group;"); }
template <int N>
__device__ __forceinline__ void cp_wait() { asm volatile("cp.async.wait_group %0;" :: "n"(N)); }

// ---------------- K1: x = concat(E[inputs], context) ----------------
__global__ __launch_bounds__(256) void build_x_kernel(
        const int* __restrict__ inputs,
        const float* __restrict__ E,
        const float* __restrict__ context) {
    int idx = blockIdx.x * blockDim.x + threadIdx.x;
    int b = idx >> 11;
    int j = idx & 2047;
    float v;
    if (j < HH) v = E[(size_t)inputs[b] * HH + j];
    else        v = context[b * HH + (j - HH)];
    g_x[idx] = v;
}

// ---------------- multi-problem precise (3xTF32) 64xN GEMM ----------------
struct Prob {
    const float* X;   // [64, k] rows with stride xs
    const float* W;   // TRANS=0: [n, k] stride ws; TRANS=1: [k, n] stride ws
    float* C;         // [64, n] stride n
    int xs, ws, n, k;
};
struct Probs4 { Prob p[4]; };

template <bool TRANS>
__global__ __launch_bounds__(256) void gemm_multi_kernel(Probs4 P) {
    const Prob pr = P.p[blockIdx.y];
    const float* __restrict__ X = pr.X;
    const float* __restrict__ W = pr.W;
    float* __restrict__ C = pr.C;
    const int xs = pr.xs, ws = pr.ws, N = pr.n, K = pr.k;

    extern __shared__ float smem[];
    float* Abase = smem;
    float* Bbase = smem + STAGES * STAGE_FLOATS;

    const int tid = threadIdx.x;
    const int n0 = blockIdx.x * 64;
    const int warp = tid >> 5, lane = tid & 31;
    const int wm = (warp & 3) * 16;
    const int wn = (warp >> 2) * 32;
    const int g = lane >> 2, tg = lane & 3;

    const int nk = K >> 5;

    auto load_stage = [&](int s, int kt) {
        int k0 = kt << 5;
        float* As = Abase + s * STAGE_FLOATS;
        float* Bs = Bbase + s * STAGE_FLOATS;
#pragma unroll
        for (int i = 0; i < 2; i++) {
            int c = tid + i * 256;
            int m = c >> 3, cc = c & 7;
            cp_async16(As + m * 36 + cc * 4, X + (size_t)m * xs + k0 + cc * 4);
        }
        if (!TRANS) {
#pragma unroll
            for (int i = 0; i < 2; i++) {
                int c = tid + i * 256;
                int n = c >> 3, cc = c & 7;
                int gn = n0 + n;
                cp_async16_z(Bs + n * 36 + cc * 4, W + (size_t)gn * ws + k0 + cc * 4, gn < N);
            }
        } else {
#pragma unroll
            for (int i = 0; i < 2; i++) {
                int c = tid + i * 256;
                int kk = c >> 4, cc = c & 15;
                int gn = n0 + cc * 4;
                cp_async16_z(Bs + kk * 68 + cc * 4, W + (size_t)(k0 + kk) * ws + gn, gn < N);
            }
        }
        cp_commit();
    };

    float acc[4][4];
#pragma unroll
    for (int i = 0; i < 4; i++)
#pragma unroll
        for (int j = 0; j < 4; j++) acc[i][j] = 0.f;

    for (int s = 0; s < STAGES - 1; s++) load_stage(s, s);

    for (int kt = 0; kt < nk; kt++) {
        cp_wait<STAGES - 2>();
        __syncthreads();
        const float* As = Abase + (kt & (STAGES - 1)) * STAGE_FLOATS;
        const float* Bs = Bbase + (kt & (STAGES - 1)) * STAGE_FLOATS;

#pragma unroll
        for (int ks = 0; ks < 4; ks++) {
            float af[4];
            af[0] = As[(wm + g) * 36 + ks * 8 + tg];
            af[1] = As[(wm + g + 8) * 36 + ks * 8 + tg];
            af[2] = As[(wm + g) * 36 + ks * 8 + tg + 4];
            af[3] = As[(wm + g + 8) * 36 + ks * 8 + tg + 4];
            uint32_t ah[4], al[4];
#pragma unroll
            for (int i = 0; i < 4; i++) {
                ah[i] = f2tf32(af[i]);
                al[i] = f2tf32(af[i] - __uint_as_float(ah[i]));
            }
#pragma unroll
            for (int nt = 0; nt < 4; nt++) {
                float bf0, bf1;
                if (!TRANS) {
                    bf0 = Bs[(wn + nt * 8 + g) * 36 + ks * 8 + tg];
                    bf1 = Bs[(wn + nt * 8 + g) * 36 + ks * 8 + tg + 4];
                } else {
                    bf0 = Bs[(ks * 8 + tg) * 68 + wn + nt * 8 + g];
                    bf1 = Bs[(ks * 8 + tg + 4) * 68 + wn + nt * 8 + g];
                }
                uint32_t bh0 = f2tf32(bf0), bh1 = f2tf32(bf1);
                uint32_t bl0 = f2tf32(bf0 - __uint_as_float(bh0));
                uint32_t bl1 = f2tf32(bf1 - __uint_as_float(bh1));
                mma_tf32(acc[nt], ah[0], ah[1], ah[2], ah[3], bl0, bl1);
                mma_tf32(acc[nt], al[0], al[1], al[2], al[3], bh0, bh1);
                mma_tf32(acc[nt], ah[0], ah[1], ah[2], ah[3], bh0, bh1);
            }
        }
        __syncthreads();
        if (kt + STAGES - 1 < nk) load_stage((kt + STAGES - 1) & (STAGES - 1), kt + STAGES - 1);
        else cp_commit();
    }

#pragma unroll
    for (int nt = 0; nt < 4; nt++) {
        int col = wn + nt * 8 + 2 * tg;
        int row0 = wm + g;
        int row1 = row0 + 8;
#pragma unroll
        for (int cc = 0; cc < 2; cc++) {
            int gn = n0 + col + cc;
            if (gn < N) {
                C[(size_t)row0 * N + gn] = acc[nt][cc];
                C[(size_t)row1 * N + gn] = acc[nt][2 + cc];
            }
        }
    }
}

// ---------------- wide Wo GEMM: logits = tanh(y @ Wo^T + bo) ----------------
// TILE 64x128, 3-stage cp.async, raw-fp32-bits fed as TF32 (no cvt).
__global__ __launch_bounds__(256) void gemm_wo_kernel(
        const float* __restrict__ X,    // [64, 2048]
        const float* __restrict__ W,    // [V, 2048]
        const float* __restrict__ bias, // [V]
        float* __restrict__ C) {        // [64, V]
    extern __shared__ float smem[];
    float* Abase = smem;                                  // [3][64][36]
    float* Bbase = smem + WO_STAGES * WO_A_FLOATS;        // [3][128][36]

    const int tid = threadIdx.x;
    const int n0 = blockIdx.x * 128;
    const int warp = tid >> 5, lane = tid & 31;
    const int wm = (warp & 3) * 16;
    const int wn = (warp >> 2) * 64;
    const int g = lane >> 2, tg = lane & 3;

    const int K = 2 * HH;
    const int nk = K >> 5;       // 64

    auto load_stage = [&](int s, int kt) {
        int k0 = kt << 5;
        float* As = Abase + s * WO_A_FLOATS;
        float* Bs = Bbase + s * WO_B_FLOATS;
#pragma unroll
        for (int i = 0; i < 2; i++) {
            int c = tid + i * 256;
            int m = c >> 3, cc = c & 7;
            cp_async16(As + m * 36 + cc * 4, X + (size_t)m * K + k0 + cc * 4);
        }
#pragma unroll
        for (int i = 0; i < 4; i++) {
            int c = tid + i * 256;
            int n = c >> 3, cc = c & 7;
            int gn = n0 + n;
            cp_async16_z(Bs + n * 36 + cc * 4, W + (size_t)gn * K + k0 + cc * 4, gn < VV);
        }
        cp_commit();
    };

    float acc[8][4];
#pragma unroll
    for (int i = 0; i < 8; i++)
#pragma unroll
        for (int j = 0; j < 4; j++) acc[i][j] = 0.f;

    load_stage(0, 0);
    load_stage(1, 1);

    int cur = 0, nxt = 2;
    for (int kt = 0; kt < nk; kt++) {
        cp_wait<1>();
        __syncthreads();
        const float* As = Abase + cur * WO_A_FLOATS;
        const float* Bs = Bbase + cur * WO_B_FLOATS;

#pragma unroll
        for (int ks = 0; ks < 4; ks++) {
            uint32_t a0 = __float_as_uint(As[(wm + g) * 36 + ks * 8 + tg]);
            uint32_t a1 = __float_as_uint(As[(wm + g + 8) * 36 + ks * 8 + tg]);
            uint32_t a2 = __float_as_uint(As[(wm + g) * 36 + ks * 8 + tg + 4]);
            uint32_t a3 = __float_as_uint(As[(wm + g + 8) * 36 + ks * 8 + tg + 4]);
#pragma unroll
            for (int nt = 0; nt < 8; nt++) {
                uint32_t b0 = __float_as_uint(Bs[(wn + nt * 8 + g) * 36 + ks * 8 + tg]);
                uint32_t b1 = __float_as_uint(Bs[(wn + nt * 8 + g) * 36 + ks * 8 + tg + 4]);
                mma_tf32(acc[nt], a0, a1, a2, a3, b0, b1);
            }
        }
        __syncthreads();
        if (kt + 2 < nk) load_stage(nxt, kt + 2);
        else cp_commit();
        cur = (cur == 2) ? 0 : cur + 1;
        nxt = (nxt == 2) ? 0 : nxt + 1;
    }

#pragma unroll
    for (int nt = 0; nt < 8; nt++) {
        int col = wn + nt * 8 + 2 * tg;
        int row0 = wm + g;
        int row1 = row0 + 8;
#pragma unroll
        for (int cc = 0; cc < 2; cc++) {
            int gn = n0 + col + cc;
            if (gn < VV) {
                float bv = bias[gn];
                C[(size_t)row0 * VV + gn] = tanhf(acc[nt][cc] + bv);
                C[(size_t)row1 * VV + gn] = tanhf(acc[nt][2 + cc] + bv);
            }
        }
    }
}

// ---------------- GRU gates (sums gi partials, adds biases) ----------------
__global__ __launch_bounds__(256) void gru_gates_kernel(
        const float* __restrict__ giA, const float* __restrict__ giB,
        const float* __restrict__ bi,
        const float* __restrict__ gh, const float* __restrict__ bh,
        const float* __restrict__ hprev, float* __restrict__ hnew) {
    int idx = blockIdx.x * blockDim.x + threadIdx.x;  // B*H
    int b = idx >> 10;
    int h = idx & 1023;
    size_t base = (size_t)b * 3 * HH;
    float ir = giA[base + h]           + giB[base + h]           + bi[h];
    float iz = giA[base + HH + h]      + giB[base + HH + h]      + bi[HH + h];
    float in_ = giA[base + 2 * HH + h] + giB[base + 2 * HH + h]  + bi[2 * HH + h];
    float hr = gh[base + h]           + bh[h];
    float hz = gh[base + HH + h]      + bh[HH + h];
    float hn = gh[base + 2 * HH + h]  + bh[2 * HH + h];
    float r = 1.f / (1.f + __expf(-(ir + hr)));
    float z = 1.f / (1.f + __expf(-(iz + hz)));
    float n = tanhf(in_ + r * hn);
    hnew[idx] = (1.f - z) * n + z * hprev[idx];
}

// ---------------- new_hidden = stack(h0,h1) + embedded ----------------
__global__ __launch_bounds__(256) void new_hidden_kernel(float* __restrict__ hid_out) {
    int idx = blockIdx.x * blockDim.x + threadIdx.x;
    int b = idx >> 10;
    int h = idx & 1023;
    float emb = g_x[b * 2 * HH + h];
    hid_out[idx] = g_h0[idx] + emb;
    hid_out[BB * HH + idx] = g_h1[idx] + emb;
}

// ---------------- attention partial (flash pass) ----------------
__global__ __launch_bounds__(128) void attn_partial_kernel(const float* __restrict__ enc) {
    const int b = blockIdx.y;
    const int warp = threadIdx.x >> 5, lane = threadIdx.x & 31;
    const int seg = blockIdx.x * 4 + warp;
    const size_t tstride = (size_t)BB * HH;

    float4 uu[8];
#pragma unroll
    for (int i = 0; i < 8; i++) {
        int off = b * HH + i * 128 + lane * 4;
        float4 u0 = *(const float4*)&g_up[off];
        float4 u1 = *(const float4*)&g_up[BB * HH + off];
        float4 u2 = *(const float4*)&g_up[2 * BB * HH + off];
        float4 u3 = *(const float4*)&g_up[3 * BB * HH + off];
        uu[i].x = u0.x + u1.x + u2.x + u3.x;
        uu[i].y = u0.y + u1.y + u2.y + u3.y;
        uu[i].z = u0.z + u1.z + u2.z + u3.z;
        uu[i].w = u0.w + u1.w + u2.w + u3.w;
    }

    float4 cc[8];
#pragma unroll
    for (int i = 0; i < 8; i++) cc[i] = make_float4(0.f, 0.f, 0.f, 0.f);

    float m = -1e30f, l = 0.f;
    const int t0 = seg * 32;
    const float* ep = enc + ((size_t)t0 * BB + b) * HH;

    float4 eA[8], eB[8];
#pragma unroll
    for (int i = 0; i < 8; i++)
        eA[i] = *(const float4*)&ep[i * 128 + lane * 4];

    auto process = [&](const float4 (&e)[8], int t) {
        float d = 0.f;
#pragma unroll
        for (int i = 0; i < 8; i++) {
            d += e[i].x * uu[i].x + e[i].y * uu[i].y +
                 e[i].z * uu[i].z + e[i].w * uu[i].w;
        }
#pragma unroll
        for (int o = 16; o; o >>= 1) d += __shfl_xor_sync(0xffffffffu, d, o);
        if (lane == 0) g_scores[b * TT + t] = d;
        float mn = fmaxf(m, d);
        float corr = __expf(m - mn);
        float p = __expf(d - mn);
        l = l * corr + p;
        m = mn;
#pragma unroll
        for (int i = 0; i < 8; i++) {
            cc[i].x = cc[i].x * corr + p * e[i].x;
            cc[i].y = cc[i].y * corr + p * e[i].y;
            cc[i].z = cc[i].z * corr + p * e[i].z;
            cc[i].w = cc[i].w * corr + p * e[i].w;
        }
    };

    for (int tt = 0; tt < 32; tt += 2) {
        const float* ep1 = ep + tstride;
#pragma unroll
        for (int i = 0; i < 8; i++)
            eB[i] = *(const float4*)&ep1[i * 128 + lane * 4];
        process(eA, t0 + tt);
        const float* ep2 = ep + 2 * tstride;
        if (tt + 2 < 32) {
#pragma unroll
            for (int i = 0; i < 8; i++)
                eA[i] = *(const float4*)&ep2[i * 128 + lane * 4];
        }
        process(eB, t0 + tt + 1);
        ep = ep2;
    }

    float* cp = &g_ctxpart[((size_t)b * 64 + seg) * HH];
#pragma unroll
    for (int i = 0; i < 8; i++)
        *(float4*)&cp[i * 128 + lane * 4] = cc[i];
    if (lane == 0) {
        g_mpart[b * 64 + seg] = m;
        g_lpart[b * 64 + seg] = l;
    }
}

// ---------------- combine partials -> context; build y ----------------
__global__ __launch_bounds__(256) void attn_combine_kernel(float* __restrict__ ctx_out) {
    int b = blockIdx.x;
    int tid = threadIdx.x;
    __shared__ float sm[64], sl[64], sw[64];
    __shared__ float sML[2];
    if (tid < 64) {
        sm[tid] = g_mpart[b * 64 + tid];
        sl[tid] = g_lpart[b * 64 + tid];
    }
    __syncthreads();
    if (tid == 0) {
        float M = -1e30f;
        for (int s = 0; s < 64; s++) M = fmaxf(M, sm[s]);
        float L = 0.f;
        for (int s = 0; s < 64; s++) L += sl[s] * __expf(sm[s] - M);
        sML[0] = M; sML[1] = L;
        g_M[b] = M; g_L[b] = L;
    }
    __syncthreads();
    if (tid < 64) sw[tid] = __expf(sm[tid] - sML[0]) / sML[1];
    __syncthreads();

    int h = tid * 4;
    float4 a = make_float4(0.f, 0.f, 0.f, 0.f);
    for (int s = 0; s < 64; s++) {
        float4 v = *(const float4*)&g_ctxpart[((size_t)b * 64 + s) * HH + h];
        float w = sw[s];
        a.x += w * v.x; a.y += w * v.y; a.z += w * v.z; a.w += w * v.w;
    }
    *(float4*)&ctx_out[b * HH + h] = a;
    *(float4*)&g_y[b * 2 * HH + HH + h] = a;
    float4 o = *(const float4*)&g_h1[b * HH + h];
    *(float4*)&g_y[b * 2 * HH + h] = o;
}

// ---------------- attn probs to output ----------------
__global__ __launch_bounds__(256) void attn_write_kernel(float* __restrict__ attn_out) {
    int idx = blockIdx.x * blockDim.x + threadIdx.x;
    int b = idx >> 11;
    attn_out[idx] = __expf(g_scores[idx] - g_M[b]) / g_L[b];
}

// ---------------- log-sum-exp over V per batch ----------------
__global__ __launch_bounds__(256) void lse_kernel() {
    int b = blockIdx.x;
    int tid = threadIdx.x;
    float m = -1e30f, l = 0.f;
    const float* row = &g_logits[(size_t)b * VV];
    for (int v = tid; v < VV; v += 256) {
        float x = row[v];
        if (x > m) {
            l = l * __expf(m - x) + 1.f;
            m = x;
        } else {
            l += __expf(x - m);
        }
    }
#pragma unroll
    for (int o = 16; o; o >>= 1) {
        float mo = __shfl_xor_sync(0xffffffffu, m, o);
        float lo = __shfl_xor_sync(0xffffffffu, l, o);
        float M = fmaxf(m, mo);
        l = l * __expf(m - M) + lo * __expf(mo - M);
        m = M;
    }
    __shared__ float wm[8], wl[8];
    if ((tid & 31) == 0) { wm[tid >> 5] = m; wl[tid >> 5] = l; }
    __syncthreads();
    if (tid == 0) {
        float M = -1e30f;
        for (int w = 0; w < 8; w++) M = fmaxf(M, wm[w]);
        float L = 0.f;
        for (int w = 0; w < 8; w++) L += wl[w] * __expf(wm[w] - M);
        g_lse[b] = M + logf(L);
    }
}

// ---------------- out = logits - lse ----------------
__global__ __launch_bounds__(256) void out_write_kernel(float* __restrict__ out) {
    int idx = blockIdx.x * blockDim.x + threadIdx.x;
    if (idx >= BB * VV) return;
    int b = idx / VV;
    out[idx] = g_logits[idx] - g_lse[b];
}

// ---------------- launch ----------------
extern "C" void kernel_launch(void* const* d_in, const int* in_sizes, int n_in,
                              void* d_out, int out_size) {
    const int*   inputs  = (const int*)d_in[0];
    const float* hidden  = (const float*)d_in[1];
    const float* context = (const float*)d_in[2];
    const float* enc     = (const float*)d_in[3];
    const float* E       = (const float*)d_in[4];
    const float* W_ih0   = (const float*)d_in[5];
    const float* W_hh0   = (const float*)d_in[6];
    const float* b_ih0   = (const float*)d_in[7];
    const float* b_hh0   = (const float*)d_in[8];
    const float* W_ih1   = (const float*)d_in[9];
    const float* W_hh1   = (const float*)d_in[10];
    const float* b_ih1   = (const float*)d_in[11];
    const float* b_hh1   = (const float*)d_in[12];
    const float* Wa      = (const float*)d_in[13];
    // d_in[14] = ba: softmax-invariant per-batch constant -> unused
    const float* Wo      = (const float*)d_in[15];
    const float* bo      = (const float*)d_in[16];

    float* out0     = (float*)d_out;
    float* hid_out  = out0 + (size_t)BB * VV;
    float* ctx_out  = hid_out + 2 * BB * HH;
    float* attn_out = ctx_out + BB * HH;

    void *p_x, *p_gi, *p_gia, *p_gh, *p_gh1, *p_h0, *p_h1, *p_up, *p_y, *p_logits;
    cudaGetSymbolAddress(&p_x, g_x);
    cudaGetSymbolAddress(&p_gi, g_gi);
    cudaGetSymbolAddress(&p_gia, g_gia);
    cudaGetSymbolAddress(&p_gh, g_gh);
    cudaGetSymbolAddress(&p_gh1, g_gh1);
    cudaGetSymbolAddress(&p_h0, g_h0);
    cudaGetSymbolAddress(&p_h1, g_h1);
    cudaGetSymbolAddress(&p_up, g_up);
    cudaGetSymbolAddress(&p_y, g_y);
    cudaGetSymbolAddress(&p_logits, g_logits);
    float* xx  = (float*)p_x;
    float* gi  = (float*)p_gi;
    float* gia = (float*)p_gia;
    float* gh  = (float*)p_gh;
    float* gh1 = (float*)p_gh1;
    float* h0  = (float*)p_h0;
    float* h1  = (float*)p_h1;
    float* up  = (float*)p_up;
    float* yy  = (float*)p_y;
    float* lg  = (float*)p_logits;

    static bool attr_done = false;
    if (!attr_done) {
        cudaFuncSetAttribute(gemm_multi_kernel<false>,
                             cudaFuncAttributeMaxDynamicSharedMemorySize, GEMM_SMEM_BYTES);
        cudaFuncSetAttribute(gemm_multi_kernel<true>,
                             cudaFuncAttributeMaxDynamicSharedMemorySize, GEMM_SMEM_BYTES);
        cudaFuncSetAttribute(gemm_wo_kernel,
                             cudaFuncAttributeMaxDynamicSharedMemorySize, WO_SMEM_BYTES);
        attr_done = true;
    }

    // 1) x = concat(E[inputs], context)
    build_x_kernel<<<(BB * 2 * HH) / 256, 256>>>(inputs, E, context);

    // 2) G1: gi0 split-K (emb half, ctx half), gh0, gh1 — one launch, grid 192
    {
        Probs4 P;
        P.p[0] = { xx,            W_ih0,        gi,  2 * HH, 2 * HH, 3 * HH, HH };  // emb @ W_ih0[:, :H]
        P.p[1] = { xx + HH,       W_ih0 + HH,   gia, 2 * HH, 2 * HH, 3 * HH, HH };  // ctx @ W_ih0[:, H:]
        P.p[2] = { hidden,        W_hh0,        gh,  HH,     HH,     3 * HH, HH };
        P.p[3] = { hidden + BB * HH, W_hh1,     gh1, HH,     HH,     3 * HH, HH };
        gemm_multi_kernel<false><<<dim3(48, 4), 256, GEMM_SMEM_BYTES>>>(P);
    }
    gru_gates_kernel<<<(BB * HH) / 256, 256>>>(gi, gia, b_ih0, gh, b_hh0, hidden, h0);

    // 3) G2: gi1 split-K=2 — grid 96
    {
        Probs4 P;
        P.p[0] = { h0,                 W_ih1,              gi,  HH, HH, 3 * HH, HH / 2 };
        P.p[1] = { h0 + HH / 2,        W_ih1 + HH / 2,     gia, HH, HH, 3 * HH, HH / 2 };
        P.p[2] = P.p[0]; P.p[3] = P.p[0];
        gemm_multi_kernel<false><<<dim3(48, 2), 256, GEMM_SMEM_BYTES>>>(P);
    }
    gru_gates_kernel<<<(BB * HH) / 256, 256>>>(gi, gia, b_ih1, gh1, b_hh1, hidden + BB * HH, h1);

    // 4) new_hidden
    new_hidden_kernel<<<(BB * HH) / 256, 256>>>(hid_out);

    // 5) u = h1 @ Wa, split-K=4 — grid 64 (Wa is [K,N] -> TRANS)
    {
        Probs4 P;
        P.p[0] = { h1,            Wa,                       up,              HH, HH, HH, HH / 4 };
        P.p[1] = { h1 + 256,      Wa + (size_t)256 * HH,    up + BB * HH,    HH, HH, HH, HH / 4 };
        P.p[2] = { h1 + 512,      Wa + (size_t)512 * HH,    up + 2 * BB * HH, HH, HH, HH, HH / 4 };
        P.p[3] = { h1 + 768,      Wa + (size_t)768 * HH,    up + 3 * BB * HH, HH, HH, HH, HH / 4 };
        gemm_multi_kernel<true><<<dim3(16, 4), 256, GEMM_SMEM_BYTES>>>(P);
    }

    // 6) flash-attention pass
    attn_partial_kernel<<<dim3(16, BB), 128>>>(enc);
    attn_combine_kernel<<<BB, 256>>>(ctx_out);
    attn_write_kernel<<<(BB * TT) / 256, 256>>>(attn_out);

    // 7) logits = tanh(y @ Wo^T + bo) — wide raw-TF32 kernel, grid 393
    gemm_wo_kernel<<<(VV + 127) / 128, 256, WO_SMEM_BYTES>>>(yy, Wo, bo, lg);

    // 8) log_softmax
    lse_kernel<<<BB, 256>>>();
    out_write_kernel<<<(BB * VV + 255) / 256, 256>>>(out0);
}

// round 8
// speedup vs baseline: 3.9210x; 1.0459x over previous
#include <cuda_runtime.h>
#include <cstdint>
#include <cstddef>

#define HH 1024
#define VV 50257
#define BB 64
#define TT 2048

#define STAGES 4
#define STAGE_FLOATS 2304                    // A: 64*36; B: max(64*36, 32*68)
#define GEMM_SMEM_BYTES (STAGES * 2 * STAGE_FLOATS * 4)   // 73728

#define WO_STAGES 3
#define WO_A_FLOATS 2304                     // 64*36
#define WO_B_FLOATS 4608                     // 128*36
#define WO_SMEM_BYTES (WO_STAGES * (WO_A_FLOATS + WO_B_FLOATS) * 4)  // 82944

// ---------------- scratch (device globals: no allocation) ----------------
__device__ float g_x[BB * 2 * HH];          // [B,2H] concat(embedded, context)
__device__ float g_gi[BB * 3 * HH];         // gi partial A
__device__ float g_gia[BB * 3 * HH];        // gi partial B
__device__ float g_gh[BB * 3 * HH];         // gh layer-0
__device__ float g_gh1[BB * 3 * HH];        // gh layer-1 (computed early)
__device__ float g_h0[BB * HH];
__device__ float g_h1[BB * HH];
__device__ float g_up[4 * BB * HH];         // u split-K partials
__device__ float g_scores[BB * TT];
__device__ float g_ctxpart[(size_t)BB * 64 * HH];
__device__ float g_mpart[BB * 64];
__device__ float g_lpart[BB * 64];
__device__ float g_y[BB * 2 * HH];          // [B,2H] concat(output, context)
__device__ float g_logits[(size_t)BB * VV];
__device__ float g_lse[BB];

// ---------------- helpers ----------------
// split float2 -> packed bf16x2 (hi, lo) pair; low half = .x (lower k index)
__device__ __forceinline__ void split_bf16x2(float2 p, uint32_t& hi, uint32_t& lo) {
    asm("cvt.rn.bf16x2.f32 %0, %1, %2;" : "=r"(hi) : "f"(p.y), "f"(p.x));
    float h0 = __uint_as_float(hi << 16);
    float h1 = __uint_as_float(hi & 0xffff0000u);
    float r0 = p.x - h0;
    float r1 = p.y - h1;
    asm("cvt.rn.bf16x2.f32 %0, %1, %2;" : "=r"(lo) : "f"(r1), "f"(r0));
}

__device__ __forceinline__ void mma_bf16(float c[4], uint32_t a0, uint32_t a1,
                                         uint32_t a2, uint32_t a3,
                                         uint32_t b0, uint32_t b1) {
    asm volatile(
        "mma.sync.aligned.m16n8k16.row.col.f32.bf16.bf16.f32 "
        "{%0,%1,%2,%3}, {%4,%5,%6,%7}, {%8,%9}, {%0,%1,%2,%3};"
        : "+f"(c[0]), "+f"(c[1]), "+f"(c[2]), "+f"(c[3])
        : "r"(a0), "r"(a1), "r"(a2), "r"(a3), "r"(b0), "r"(b1));
}

__device__ __forceinline__ void mma_tf32(float c[4], uint32_t a0, uint32_t a1,
                                         uint32_t a2, uint32_t a3,
                                         uint32_t b0, uint32_t b1) {
    asm volatile(
        "mma.sync.aligned.m16n8k8.row.col.f32.tf32.tf32.f32 "
        "{%0,%1,%2,%3}, {%4,%5,%6,%7}, {%8,%9}, {%0,%1,%2,%3};"
        : "+f"(c[0]), "+f"(c[1]), "+f"(c[2]), "+f"(c[3])
        : "r"(a0), "r"(a1), "r"(a2), "r"(a3), "r"(b0), "r"(b1));
}

__device__ __forceinline__ void cp_async16(float* dst, const float* src) {
    uint32_t s = (uint32_t)__cvta_generic_to_shared(dst);
    asm volatile("cp.async.cg.shared.global [%0], [%1], 16;" :: "r"(s), "l"(src));
}
__device__ __forceinline__ void cp_async16_z(float* dst, const float* src, bool valid) {
    uint32_t s = (uint32_t)__cvta_generic_to_shared(dst);
    int sz = valid ? 16 : 0;
    asm volatile("cp.async.cg.shared.global [%0], [%1], 16, %2;" :: "r"(s), "l"(src), "r"(sz));
}
__device__ __forceinline__ void cp_commit() { asm volatile("cp.async.commit_group;"); }
template <int N>
__device__ __forceinline__ void cp_wait() { asm volatile("cp.async.wait_group %0;" :: "n"(N)); }

// ---------------- K1: x = concat(E[inputs], context) ----------------
__global__ __launch_bounds__(256) void build_x_kernel(
        const int* __restrict__ inputs,
        const float* __restrict__ E,
        const float* __restrict__ context) {
    int idx = blockIdx.x * blockDim.x + threadIdx.x;
    int b = idx >> 11;
    int j = idx & 2047;
    float v;
    if (j < HH) v = E[(size_t)inputs[b] * HH + j];
    else        v = context[b * HH + (j - HH)];
    g_x[idx] = v;
}

// ---------------- multi-problem precise (3xBF16) 64xN GEMM ----------------
struct Prob {
    const float* X;   // [64, k] rows with stride xs
    const float* W;   // TRANS=0: [n, k] stride ws; TRANS=1: [k, n] stride ws
    float* C;         // [64, n] stride n
    int xs, ws, n, k;
};
struct Probs4 { Prob p[4]; };

template <bool TRANS>
__global__ __launch_bounds__(256) void gemm_multi_kernel(Probs4 P) {
    const Prob pr = P.p[blockIdx.y];
    const float* __restrict__ X = pr.X;
    const float* __restrict__ W = pr.W;
    float* __restrict__ C = pr.C;
    const int xs = pr.xs, ws = pr.ws, N = pr.n, K = pr.k;

    extern __shared__ float smem[];
    float* Abase = smem;
    float* Bbase = smem + STAGES * STAGE_FLOATS;

    const int tid = threadIdx.x;
    const int n0 = blockIdx.x * 64;
    const int warp = tid >> 5, lane = tid & 31;
    const int wm = (warp & 3) * 16;
    const int wn = (warp >> 2) * 32;
    const int g = lane >> 2, tg = lane & 3;

    const int nk = K >> 5;

    auto load_stage = [&](int s, int kt) {
        int k0 = kt << 5;
        float* As = Abase + s * STAGE_FLOATS;
        float* Bs = Bbase + s * STAGE_FLOATS;
#pragma unroll
        for (int i = 0; i < 2; i++) {
            int c = tid + i * 256;
            int m = c >> 3, cc = c & 7;
            cp_async16(As + m * 36 + cc * 4, X + (size_t)m * xs + k0 + cc * 4);
        }
        if (!TRANS) {
#pragma unroll
            for (int i = 0; i < 2; i++) {
                int c = tid + i * 256;
                int n = c >> 3, cc = c & 7;
                int gn = n0 + n;
                cp_async16_z(Bs + n * 36 + cc * 4, W + (size_t)gn * ws + k0 + cc * 4, gn < N);
            }
        } else {
#pragma unroll
            for (int i = 0; i < 2; i++) {
                int c = tid + i * 256;
                int kk = c >> 4, cc = c & 15;
                int gn = n0 + cc * 4;
                cp_async16_z(Bs + kk * 68 + cc * 4, W + (size_t)(k0 + kk) * ws + gn, gn < N);
            }
        }
        cp_commit();
    };

    float acc[4][4];
#pragma unroll
    for (int i = 0; i < 4; i++)
#pragma unroll
        for (int j = 0; j < 4; j++) acc[i][j] = 0.f;

    for (int s = 0; s < STAGES - 1; s++) load_stage(s, s);

    for (int kt = 0; kt < nk; kt++) {
        cp_wait<STAGES - 2>();
        __syncthreads();
        const float* As = Abase + (kt & (STAGES - 1)) * STAGE_FLOATS;
        const float* Bs = Bbase + (kt & (STAGES - 1)) * STAGE_FLOATS;

#pragma unroll
        for (int ks2 = 0; ks2 < 2; ks2++) {
            const int kb = ks2 * 16;
            uint32_t ah[4], al[4];
            {
                float2 p;
                p = *(const float2*)&As[(wm + g) * 36 + kb + 2 * tg];
                split_bf16x2(p, ah[0], al[0]);
                p = *(const float2*)&As[(wm + g + 8) * 36 + kb + 2 * tg];
                split_bf16x2(p, ah[1], al[1]);
                p = *(const float2*)&As[(wm + g) * 36 + kb + 8 + 2 * tg];
                split_bf16x2(p, ah[2], al[2]);
                p = *(const float2*)&As[(wm + g + 8) * 36 + kb + 8 + 2 * tg];
                split_bf16x2(p, ah[3], al[3]);
            }
#pragma unroll
            for (int nt = 0; nt < 4; nt++) {
                float2 q0, q1;
                if (!TRANS) {
                    int n = wn + nt * 8 + g;
                    q0 = *(const float2*)&Bs[n * 36 + kb + 2 * tg];
                    q1 = *(const float2*)&Bs[n * 36 + kb + 8 + 2 * tg];
                } else {
                    int n = wn + nt * 8 + g;
                    q0.x = Bs[(kb + 2 * tg) * 68 + n];
                    q0.y = Bs[(kb + 2 * tg + 1) * 68 + n];
                    q1.x = Bs[(kb + 8 + 2 * tg) * 68 + n];
                    q1.y = Bs[(kb + 9 + 2 * tg) * 68 + n];
                }
                uint32_t bh0, bl0, bh1, bl1;
                split_bf16x2(q0, bh0, bl0);
                split_bf16x2(q1, bh1, bl1);
                mma_bf16(acc[nt], ah[0], ah[1], ah[2], ah[3], bl0, bl1);
                mma_bf16(acc[nt], al[0], al[1], al[2], al[3], bh0, bh1);
                mma_bf16(acc[nt], ah[0], ah[1], ah[2], ah[3], bh0, bh1);
            }
        }
        __syncthreads();
        if (kt + STAGES - 1 < nk) load_stage((kt + STAGES - 1) & (STAGES - 1), kt + STAGES - 1);
        else cp_commit();
    }

#pragma unroll
    for (int nt = 0; nt < 4; nt++) {
        int col = wn + nt * 8 + 2 * tg;
        int row0 = wm + g;
        int row1 = row0 + 8;
#pragma unroll
        for (int cc = 0; cc < 2; cc++) {
            int gn = n0 + col + cc;
            if (gn < N) {
                C[(size_t)row0 * N + gn] = acc[nt][cc];
                C[(size_t)row1 * N + gn] = acc[nt][2 + cc];
            }
        }
    }
}

// ---------------- wide Wo GEMM: logits = tanh(y @ Wo^T + bo) ----------------
// TILE 64x128, 3-stage cp.async, raw-fp32-bits fed as TF32 (no cvt).
__global__ __launch_bounds__(256) void gemm_wo_kernel(
        const float* __restrict__ X,    // [64, 2048]
        const float* __restrict__ W,    // [V, 2048]
        const float* __restrict__ bias, // [V]
        float* __restrict__ C) {        // [64, V]
    extern __shared__ float smem[];
    float* Abase = smem;                                  // [3][64][36]
    float* Bbase = smem + WO_STAGES * WO_A_FLOATS;        // [3][128][36]

    const int tid = threadIdx.x;
    const int n0 = blockIdx.x * 128;
    const int warp = tid >> 5, lane = tid & 31;
    const int wm = (warp & 3) * 16;
    const int wn = (warp >> 2) * 64;
    const int g = lane >> 2, tg = lane & 3;

    const int K = 2 * HH;
    const int nk = K >> 5;       // 64

    auto load_stage = [&](int s, int kt) {
        int k0 = kt << 5;
        float* As = Abase + s * WO_A_FLOATS;
        float* Bs = Bbase + s * WO_B_FLOATS;
#pragma unroll
        for (int i = 0; i < 2; i++) {
            int c = tid + i * 256;
            int m = c >> 3, cc = c & 7;
            cp_async16(As + m * 36 + cc * 4, X + (size_t)m * K + k0 + cc * 4);
        }
#pragma unroll
        for (int i = 0; i < 4; i++) {
            int c = tid + i * 256;
            int n = c >> 3, cc = c & 7;
            int gn = n0 + n;
            cp_async16_z(Bs + n * 36 + cc * 4, W + (size_t)gn * K + k0 + cc * 4, gn < VV);
        }
        cp_commit();
    };

    float acc[8][4];
#pragma unroll
    for (int i = 0; i < 8; i++)
#pragma unroll
        for (int j = 0; j < 4; j++) acc[i][j] = 0.f;

    load_stage(0, 0);
    load_stage(1, 1);

    int cur = 0, nxt = 2;
    for (int kt = 0; kt < nk; kt++) {
        cp_wait<1>();
        __syncthreads();
        const float* As = Abase + cur * WO_A_FLOATS;
        const float* Bs = Bbase + cur * WO_B_FLOATS;

#pragma unroll
        for (int ks = 0; ks < 4; ks++) {
            uint32_t a0 = __float_as_uint(As[(wm + g) * 36 + ks * 8 + tg]);
            uint32_t a1 = __float_as_uint(As[(wm + g + 8) * 36 + ks * 8 + tg]);
            uint32_t a2 = __float_as_uint(As[(wm + g) * 36 + ks * 8 + tg + 4]);
            uint32_t a3 = __float_as_uint(As[(wm + g + 8) * 36 + ks * 8 + tg + 4]);
#pragma unroll
            for (int nt = 0; nt < 8; nt++) {
                uint32_t b0 = __float_as_uint(Bs[(wn + nt * 8 + g) * 36 + ks * 8 + tg]);
                uint32_t b1 = __float_as_uint(Bs[(wn + nt * 8 + g) * 36 + ks * 8 + tg + 4]);
                mma_tf32(acc[nt], a0, a1, a2, a3, b0, b1);
            }
        }
        __syncthreads();
        if (kt + 2 < nk) load_stage(nxt, kt + 2);
        else cp_commit();
        cur = (cur == 2) ? 0 : cur + 1;
        nxt = (nxt == 2) ? 0 : nxt + 1;
    }

#pragma unroll
    for (int nt = 0; nt < 8; nt++) {
        int col = wn + nt * 8 + 2 * tg;
        int row0 = wm + g;
        int row1 = row0 + 8;
#pragma unroll
        for (int cc = 0; cc < 2; cc++) {
            int gn = n0 + col + cc;
            if (gn < VV) {
                float bv = bias[gn];
                C[(size_t)row0 * VV + gn] = tanhf(acc[nt][cc] + bv);
                C[(size_t)row1 * VV + gn] = tanhf(acc[nt][2 + cc] + bv);
            }
        }
    }
}

// ---------------- GRU gates (fused: h_new, new_hidden, optional y) ---------
__global__ __launch_bounds__(256) void gru_gates_kernel(
        const float* __restrict__ giA, const float* __restrict__ giB,
        const float* __restrict__ bi,
        const float* __restrict__ gh, const float* __restrict__ bh,
        const float* __restrict__ hprev, float* __restrict__ hnew,
        float* __restrict__ hid_dst,      // new_hidden slice = hnew + emb
        float* __restrict__ y_dst) {      // if non-null: g_y[b*2H + h] = hnew
    int idx = blockIdx.x * blockDim.x + threadIdx.x;  // B*H
    int b = idx >> 10;
    int h = idx & 1023;
    size_t base = (size_t)b * 3 * HH;
    float ir = giA[base + h]           + giB[base + h]           + bi[h];
    float iz = giA[base + HH + h]      + giB[base + HH + h]      + bi[HH + h];
    float in_ = giA[base + 2 * HH + h] + giB[base + 2 * HH + h]  + bi[2 * HH + h];
    float hr = gh[base + h]           + bh[h];
    float hz = gh[base + HH + h]      + bh[HH + h];
    float hn = gh[base + 2 * HH + h]  + bh[2 * HH + h];
    float r = 1.f / (1.f + __expf(-(ir + hr)));
    float z = 1.f / (1.f + __expf(-(iz + hz)));
    float n = tanhf(in_ + r * hn);
    float v = (1.f - z) * n + z * hprev[idx];
    hnew[idx] = v;
    hid_dst[idx] = v + g_x[b * 2 * HH + h];
    if (y_dst) y_dst[b * 2 * HH + h] = v;
}

// ---------------- attention partial (flash pass) ----------------
__global__ __launch_bounds__(128) void attn_partial_kernel(const float* __restrict__ enc) {
    const int b = blockIdx.y;
    const int warp = threadIdx.x >> 5, lane = threadIdx.x & 31;
    const int seg = blockIdx.x * 4 + warp;
    const size_t tstride = (size_t)BB * HH;

    float4 uu[8];
#pragma unroll
    for (int i = 0; i < 8; i++) {
        int off = b * HH + i * 128 + lane * 4;
        float4 u0 = *(const float4*)&g_up[off];
        float4 u1 = *(const float4*)&g_up[BB * HH + off];
        float4 u2 = *(const float4*)&g_up[2 * BB * HH + off];
        float4 u3 = *(const float4*)&g_up[3 * BB * HH + off];
        uu[i].x = u0.x + u1.x + u2.x + u3.x;
        uu[i].y = u0.y + u1.y + u2.y + u3.y;
        uu[i].z = u0.z + u1.z + u2.z + u3.z;
        uu[i].w = u0.w + u1.w + u2.w + u3.w;
    }

    float4 cc[8];
#pragma unroll
    for (int i = 0; i < 8; i++) cc[i] = make_float4(0.f, 0.f, 0.f, 0.f);

    float m = -1e30f, l = 0.f;
    const int t0 = seg * 32;
    const float* ep = enc + ((size_t)t0 * BB + b) * HH;

    float4 eA[8], eB[8];
#pragma unroll
    for (int i = 0; i < 8; i++)
        eA[i] = *(const float4*)&ep[i * 128 + lane * 4];

    auto process = [&](const float4 (&e)[8], int t) {
        float d = 0.f;
#pragma unroll
        for (int i = 0; i < 8; i++) {
            d += e[i].x * uu[i].x + e[i].y * uu[i].y +
                 e[i].z * uu[i].z + e[i].w * uu[i].w;
        }
#pragma unroll
        for (int o = 16; o; o >>= 1) d += __shfl_xor_sync(0xffffffffu, d, o);
        if (lane == 0) g_scores[b * TT + t] = d;
        float mn = fmaxf(m, d);
        float corr = __expf(m - mn);
        float p = __expf(d - mn);
        l = l * corr + p;
        m = mn;
#pragma unroll
        for (int i = 0; i < 8; i++) {
            cc[i].x = cc[i].x * corr + p * e[i].x;
            cc[i].y = cc[i].y * corr + p * e[i].y;
            cc[i].z = cc[i].z * corr + p * e[i].z;
            cc[i].w = cc[i].w * corr + p * e[i].w;
        }
    };

    for (int tt = 0; tt < 32; tt += 2) {
        const float* ep1 = ep + tstride;
#pragma unroll
        for (int i = 0; i < 8; i++)
            eB[i] = *(const float4*)&ep1[i * 128 + lane * 4];
        process(eA, t0 + tt);
        const float* ep2 = ep + 2 * tstride;
        if (tt + 2 < 32) {
#pragma unroll
            for (int i = 0; i < 8; i++)
                eA[i] = *(const float4*)&ep2[i * 128 + lane * 4];
        }
        process(eB, t0 + tt + 1);
        ep = ep2;
    }

    float* cp = &g_ctxpart[((size_t)b * 64 + seg) * HH];
#pragma unroll
    for (int i = 0; i < 8; i++)
        *(float4*)&cp[i * 128 + lane * 4] = cc[i];
    if (lane == 0) {
        g_mpart[b * 64 + seg] = m;
        g_lpart[b * 64 + seg] = l;
    }
}

// ---------------- combine partials -> context, y, attn probs ----------------
__global__ __launch_bounds__(256) void attn_combine_kernel(
        float* __restrict__ ctx_out, float* __restrict__ attn_out) {
    int b = blockIdx.x;
    int tid = threadIdx.x;
    __shared__ float sm[64], sl[64], sw[64];
    __shared__ float sML[2];
    if (tid < 64) {
        sm[tid] = g_mpart[b * 64 + tid];
        sl[tid] = g_lpart[b * 64 + tid];
    }
    __syncthreads();
    if (tid == 0) {
        float M = -1e30f;
        for (int s = 0; s < 64; s++) M = fmaxf(M, sm[s]);
        float L = 0.f;
        for (int s = 0; s < 64; s++) L += sl[s] * __expf(sm[s] - M);
        sML[0] = M; sML[1] = L;
    }
    __syncthreads();
    if (tid < 64) sw[tid] = __expf(sm[tid] - sML[0]) / sML[1];
    __syncthreads();

    int h = tid * 4;
    float4 a = make_float4(0.f, 0.f, 0.f, 0.f);
    for (int s = 0; s < 64; s++) {
        float4 v = *(const float4*)&g_ctxpart[((size_t)b * 64 + s) * HH + h];
        float w = sw[s];
        a.x += w * v.x; a.y += w * v.y; a.z += w * v.z; a.w += w * v.w;
    }
    *(float4*)&ctx_out[b * HH + h] = a;
    *(float4*)&g_y[b * 2 * HH + HH + h] = a;

    // fused attn prob write
    const float M = sML[0], L = sML[1];
    for (int t = tid; t < TT; t += 256)
        attn_out[b * TT + t] = __expf(g_scores[b * TT + t] - M) / L;
}

// ---------------- log-sum-exp over V per batch ----------------
__global__ __launch_bounds__(256) void lse_kernel() {
    int b = blockIdx.x;
    int tid = threadIdx.x;
    float m = -1e30f, l = 0.f;
    const float* row = &g_logits[(size_t)b * VV];
    for (int v = tid; v < VV; v += 256) {
        float x = row[v];
        if (x > m) {
            l = l * __expf(m - x) + 1.f;
            m = x;
        } else {
            l += __expf(x - m);
        }
    }
#pragma unroll
    for (int o = 16; o; o >>= 1) {
        float mo = __shfl_xor_sync(0xffffffffu, m, o);
        float lo = __shfl_xor_sync(0xffffffffu, l, o);
        float M = fmaxf(m, mo);
        l = l * __expf(m - M) + lo * __expf(mo - M);
        m = M;
    }
    __shared__ float wm[8], wl[8];
    if ((tid & 31) == 0) { wm[tid >> 5] = m; wl[tid >> 5] = l; }
    __syncthreads();
    if (tid == 0) {
        float M = -1e30f;
        for (int w = 0; w < 8; w++) M = fmaxf(M, wm[w]);
        float L = 0.f;
        for (int w = 0; w < 8; w++) L += wl[w] * __expf(wm[w] - M);
        g_lse[b] = M + logf(L);
    }
}

// ---------------- out = logits - lse ----------------
__global__ __launch_bounds__(256) void out_write_kernel(float* __restrict__ out) {
    int idx = blockIdx.x * blockDim.x + threadIdx.x;
    if (idx >= BB * VV) return;
    int b = idx / VV;
    out[idx] = g_logits[idx] - g_lse[b];
}

// ---------------- launch ----------------
extern "C" void kernel_launch(void* const* d_in, const int* in_sizes, int n_in,
                              void* d_out, int out_size) {
    const int*   inputs  = (const int*)d_in[0];
    const float* hidden  = (const float*)d_in[1];
    const float* context = (const float*)d_in[2];
    const float* enc     = (const float*)d_in[3];
    const float* E       = (const float*)d_in[4];
    const float* W_ih0   = (const float*)d_in[5];
    const float* W_hh0   = (const float*)d_in[6];
    const float* b_ih0   = (const float*)d_in[7];
    const float* b_hh0   = (const float*)d_in[8];
    const float* W_ih1   = (const float*)d_in[9];
    const float* W_hh1   = (const float*)d_in[10];
    const float* b_ih1   = (const float*)d_in[11];
    const float* b_hh1   = (const float*)d_in[12];
    const float* Wa      = (const float*)d_in[13];
    // d_in[14] = ba: softmax-invariant per-batch constant -> unused
    const float* Wo      = (const float*)d_in[15];
    const float* bo      = (const float*)d_in[16];

    float* out0     = (float*)d_out;
    float* hid_out  = out0 + (size_t)BB * VV;
    float* ctx_out  = hid_out + 2 * BB * HH;
    float* attn_out = ctx_out + BB * HH;

    void *p_x, *p_gi, *p_gia, *p_gh, *p_gh1, *p_h0, *p_h1, *p_up, *p_y, *p_logits;
    cudaGetSymbolAddress(&p_x, g_x);
    cudaGetSymbolAddress(&p_gi, g_gi);
    cudaGetSymbolAddress(&p_gia, g_gia);
    cudaGetSymbolAddress(&p_gh, g_gh);
    cudaGetSymbolAddress(&p_gh1, g_gh1);
    cudaGetSymbolAddress(&p_h0, g_h0);
    cudaGetSymbolAddress(&p_h1, g_h1);
    cudaGetSymbolAddress(&p_up, g_up);
    cudaGetSymbolAddress(&p_y, g_y);
    cudaGetSymbolAddress(&p_logits, g_logits);
    float* xx  = (float*)p_x;
    float* gi  = (float*)p_gi;
    float* gia = (float*)p_gia;
    float* gh  = (float*)p_gh;
    float* gh1 = (float*)p_gh1;
    float* h0  = (float*)p_h0;
    float* h1  = (float*)p_h1;
    float* up  = (float*)p_up;
    float* yy  = (float*)p_y;
    float* lg  = (float*)p_logits;

    static bool attr_done = false;
    if (!attr_done) {
        cudaFuncSetAttribute(gemm_multi_kernel<false>,
                             cudaFuncAttributeMaxDynamicSharedMemorySize, GEMM_SMEM_BYTES);
        cudaFuncSetAttribute(gemm_multi_kernel<true>,
                             cudaFuncAttributeMaxDynamicSharedMemorySize, GEMM_SMEM_BYTES);
        cudaFuncSetAttribute(gemm_wo_kernel,
                             cudaFuncAttributeMaxDynamicSharedMemorySize, WO_SMEM_BYTES);
        attr_done = true;
    }

    // 1) x = concat(E[inputs], context)
    build_x_kernel<<<(BB * 2 * HH) / 256, 256>>>(inputs, E, context);

    // 2) G1: gi0 split-K (emb half, ctx half), gh0, gh1 — one launch, grid 192
    {
        Probs4 P;
        P.p[0] = { xx,            W_ih0,        gi,  2 * HH, 2 * HH, 3 * HH, HH };
        P.p[1] = { xx + HH,       W_ih0 + HH,   gia, 2 * HH, 2 * HH, 3 * HH, HH };
        P.p[2] = { hidden,        W_hh0,        gh,  HH,     HH,     3 * HH, HH };
        P.p[3] = { hidden + BB * HH, W_hh1,     gh1, HH,     HH,     3 * HH, HH };
        gemm_multi_kernel<false><<<dim3(48, 4), 256, GEMM_SMEM_BYTES>>>(P);
    }
    gru_gates_kernel<<<(BB * HH) / 256, 256>>>(gi, gia, b_ih0, gh, b_hh0,
                                               hidden, h0, hid_out, nullptr);

    // 3) G2: gi1 split-K=2 — grid 96
    {
        Probs4 P;
        P.p[0] = { h0,                 W_ih1,              gi,  HH, HH, 3 * HH, HH / 2 };
        P.p[1] = { h0 + HH / 2,        W_ih1 + HH / 2,     gia, HH, HH, 3 * HH, HH / 2 };
        P.p[2] = P.p[0]; P.p[3] = P.p[0];
        gemm_multi_kernel<false><<<dim3(48, 2), 256, GEMM_SMEM_BYTES>>>(P);
    }
    gru_gates_kernel<<<(BB * HH) / 256, 256>>>(gi, gia, b_ih1, gh1, b_hh1,
                                               hidden + BB * HH, h1,
                                               hid_out + BB * HH, yy);

    // 4) u = h1 @ Wa, split-K=4 — grid 64 (Wa is [K,N] -> TRANS)
    {
        Probs4 P;
        P.p[0] = { h1,            Wa,                       up,               HH, HH, HH, HH / 4 };
        P.p[1] = { h1 + 256,      Wa + (size_t)256 * HH,    up + BB * HH,     HH, HH, HH, HH / 4 };
        P.p[2] = { h1 + 512,      Wa + (size_t)512 * HH,    up + 2 * BB * HH, HH, HH, HH, HH / 4 };
        P.p[3] = { h1 + 768,      Wa + (size_t)768 * HH,    up + 3 * BB * HH, HH, HH, HH, HH / 4 };
        gemm_multi_kernel<true><<<dim3(16, 4), 256, GEMM_SMEM_BYTES>>>(P);
    }

    // 5) flash-attention pass + fused combine/attn-prob write
    attn_partial_kernel<<<dim3(16, BB), 128>>>(enc);
    attn_combine_kernel<<<BB, 256>>>(ctx_out, attn_out);

    // 6) logits = tanh(y @ Wo^T + bo) — wide raw-TF32 kernel, grid 393
    gemm_wo_kernel<<<(VV + 127) / 128, 256, WO_SMEM_BYTES>>>(yy, Wo, bo, lg);

    // 7) log_softmax
    lse_kernel<<<BB, 256>>>();
    out_write_kernel<<<(BB * VV + 255) / 256, 256>>>(out0);
}

// round 11
// speedup vs baseline: 4.1726x; 1.0642x over previous
#include <cuda_runtime.h>
#include <cstdint>
#include <cstddef>

#define HH 1024
#define VV 50257
#define BB 64
#define TT 2048

#define STAGES 6
#define STAGE_FLOATS 2304                    // A: 64*36; B: max(64*36, 32*68)
#define GEMM_SMEM_BYTES (STAGES * 2 * STAGE_FLOATS * 4)   // 110592

#define WO_STAGES 3
#define WO_A_FLOATS 2304                     // 64*36
#define WO_B_FLOATS 4608                     // 128*36
#define WO_SMEM_BYTES (WO_STAGES * (WO_A_FLOATS + WO_B_FLOATS) * 4)  // 82944
#define NWO ((VV + 127) / 128)               // 393 Wo blocks

// ---------------- scratch (device globals: no allocation) ----------------
__device__ float g_x[BB * 2 * HH];          // [B,2H] concat(embedded, context)
__device__ float g_gi[BB * 3 * HH];         // gi partial A
__device__ float g_gia[BB * 3 * HH];        // gi partial B
__device__ float g_gh[BB * 3 * HH];         // gh layer-0
__device__ float g_gh1[BB * 3 * HH];        // gh layer-1 (computed early)
__device__ float g_h0[BB * HH];
__device__ float g_h1[BB * HH];
__device__ float g_up[4 * BB * HH];         // u split-K partials
__device__ float g_scores[BB * TT];
__device__ float g_ctxpart[(size_t)BB * 64 * HH];
__device__ float g_mpart[BB * 64];
__device__ float g_lpart[BB * 64];
__device__ float g_y[BB * 2 * HH];          // [B,2H] concat(output, context)
__device__ float g_logits[(size_t)BB * VV];
__device__ float g_lsepart[(size_t)NWO * BB];
__device__ float g_lse[BB];

// ---------------- helpers ----------------
// split float2 -> packed bf16x2 (hi, lo) pair; low half = .x (lower k index)
__device__ __forceinline__ void split_bf16x2(float2 p, uint32_t& hi, uint32_t& lo) {
    asm("cvt.rn.bf16x2.f32 %0, %1, %2;" : "=r"(hi) : "f"(p.y), "f"(p.x));
    float h0 = __uint_as_float(hi << 16);
    float h1 = __uint_as_float(hi & 0xffff0000u);
    float r0 = p.x - h0;
    float r1 = p.y - h1;
    asm("cvt.rn.bf16x2.f32 %0, %1, %2;" : "=r"(lo) : "f"(r1), "f"(r0));
}

__device__ __forceinline__ void mma_bf16(float c[4], uint32_t a0, uint32_t a1,
                                         uint32_t a2, uint32_t a3,
                                         uint32_t b0, uint32_t b1) {
    asm volatile(
        "mma.sync.aligned.m16n8k16.row.col.f32.bf16.bf16.f32 "
        "{%0,%1,%2,%3}, {%4,%5,%6,%7}, {%8,%9}, {%0,%1,%2,%3};"
        : "+f"(c[0]), "+f"(c[1]), "+f"(c[2]), "+f"(c[3])
        : "r"(a0), "r"(a1), "r"(a2), "r"(a3), "r"(b0), "r"(b1));
}

__device__ __forceinline__ void mma_tf32(float c[4], uint32_t a0, uint32_t a1,
                                         uint32_t a2, uint32_t a3,
                                         uint32_t b0, uint32_t b1) {
    asm volatile(
        "mma.sync.aligned.m16n8k8.row.col.f32.tf32.tf32.f32 "
        "{%0,%1,%2,%3}, {%4,%5,%6,%7}, {%8,%9}, {%0,%1,%2,%3};"
        : "+f"(c[0]), "+f"(c[1]), "+f"(c[2]), "+f"(c[3])
        : "r"(a0), "r"(a1), "r"(a2), "r"(a3), "r"(b0), "r"(b1));
}

__device__ __forceinline__ void cp_async16(float* dst, const float* src) {
    uint32_t s = (uint32_t)__cvta_generic_to_shared(dst);
    asm volatile("cp.async.cg.shared.global [%0], [%1], 16;" :: "r"(s), "l"(src));
}
__device__ __forceinline__ void cp_async16_z(float* dst, const float* src, bool valid) {
    uint32_t s = (uint32_t)__cvta_generic_to_shared(dst);
    int sz = valid ? 16 : 0;
    asm volatile("cp.async.cg.shared.global [%0], [%1], 16, %2;" :: "r"(s), "l"(src), "r"(sz));
}
__device__ __forceinline__ void cp_commit() { asm volatile("cp.async.commit_group;"); }
template <int N>
__device__ __forceinline__ void cp_wait() { asm volatile("cp.async.wait_group %0;" :: "n"(N)); }

// ---------------- K1: x = concat(E[inputs], context) ----------------
__global__ __launch_bounds__(256) void build_x_kernel(
        const int* __restrict__ inputs,
        const float* __restrict__ E,
        const float* __restrict__ context) {
    int idx = blockIdx.x * blockDim.x + threadIdx.x;
    int b = idx >> 11;
    int j = idx & 2047;
    float v;
    if (j < HH) v = E[(size_t)inputs[b] * HH + j];
    else        v = context[b * HH + (j - HH)];
    g_x[idx] = v;
}

// ---------------- multi-problem precise (3xBF16) 64xN GEMM ----------------
struct Prob {
    const float* X;   // [64, k] rows with stride xs
    const float* W;   // TRANS=0: [n, k] stride ws; TRANS=1: [k, n] stride ws
    float* C;         // [64, n] stride n
    int xs, ws, n, k;
};
struct Probs4 { Prob p[4]; };

template <bool TRANS>
__global__ __launch_bounds__(256) void gemm_multi_kernel(Probs4 P) {
    const Prob pr = P.p[blockIdx.y];
    const float* __restrict__ X = pr.X;
    const float* __restrict__ W = pr.W;
    float* __restrict__ C = pr.C;
    const int xs = pr.xs, ws = pr.ws, N = pr.n, K = pr.k;

    extern __shared__ float smem[];
    float* Abase = smem;
    float* Bbase = smem + STAGES * STAGE_FLOATS;

    const int tid = threadIdx.x;
    const int n0 = blockIdx.x * 64;
    const int warp = tid >> 5, lane = tid & 31;
    const int wm = (warp & 3) * 16;
    const int wn = (warp >> 2) * 32;
    const int g = lane >> 2, tg = lane & 3;

    const int nk = K >> 5;

    auto load_stage = [&](int s, int kt) {
        int k0 = kt << 5;
        float* As = Abase + s * STAGE_FLOATS;
        float* Bs = Bbase + s * STAGE_FLOATS;
#pragma unroll
        for (int i = 0; i < 2; i++) {
            int c = tid + i * 256;
            int m = c >> 3, cc = c & 7;
            cp_async16(As + m * 36 + cc * 4, X + (size_t)m * xs + k0 + cc * 4);
        }
        if (!TRANS) {
#pragma unroll
            for (int i = 0; i < 2; i++) {
                int c = tid + i * 256;
                int n = c >> 3, cc = c & 7;
                int gn = n0 + n;
                cp_async16_z(Bs + n * 36 + cc * 4, W + (size_t)gn * ws + k0 + cc * 4, gn < N);
            }
        } else {
#pragma unroll
            for (int i = 0; i < 2; i++) {
                int c = tid + i * 256;
                int kk = c >> 4, cc = c & 15;
                int gn = n0 + cc * 4;
                cp_async16_z(Bs + kk * 68 + cc * 4, W + (size_t)(k0 + kk) * ws + gn, gn < N);
            }
        }
        cp_commit();
    };

    float acc[4][4];
#pragma unroll
    for (int i = 0; i < 4; i++)
#pragma unroll
        for (int j = 0; j < 4; j++) acc[i][j] = 0.f;

    for (int s = 0; s < STAGES - 1; s++) load_stage(s, s);

    int cur = 0, nxt = STAGES - 1;   // wrap counters (STAGES not power of 2)
    for (int kt = 0; kt < nk; kt++) {
        cp_wait<STAGES - 2>();
        __syncthreads();
        const float* As = Abase + cur * STAGE_FLOATS;
        const float* Bs = Bbase + cur * STAGE_FLOATS;

#pragma unroll
        for (int ks2 = 0; ks2 < 2; ks2++) {
            const int kb = ks2 * 16;
            uint32_t ah[4], al[4];
            {
                float2 p;
                p = *(const float2*)&As[(wm + g) * 36 + kb + 2 * tg];
                split_bf16x2(p, ah[0], al[0]);
                p = *(const float2*)&As[(wm + g + 8) * 36 + kb + 2 * tg];
                split_bf16x2(p, ah[1], al[1]);
                p = *(const float2*)&As[(wm + g) * 36 + kb + 8 + 2 * tg];
                split_bf16x2(p, ah[2], al[2]);
                p = *(const float2*)&As[(wm + g + 8) * 36 + kb + 8 + 2 * tg];
                split_bf16x2(p, ah[3], al[3]);
            }
#pragma unroll
            for (int nt = 0; nt < 4; nt++) {
                float2 q0, q1;
                if (!TRANS) {
                    int n = wn + nt * 8 + g;
                    q0 = *(const float2*)&Bs[n * 36 + kb + 2 * tg];
                    q1 = *(const float2*)&Bs[n * 36 + kb + 8 + 2 * tg];
                } else {
                    int n = wn + nt * 8 + g;
                    q0.x = Bs[(kb + 2 * tg) * 68 + n];
                    q0.y = Bs[(kb + 2 * tg + 1) * 68 + n];
                    q1.x = Bs[(kb + 8 + 2 * tg) * 68 + n];
                    q1.y = Bs[(kb + 9 + 2 * tg) * 68 + n];
                }
                uint32_t bh0, bl0, bh1, bl1;
                split_bf16x2(q0, bh0, bl0);
                split_bf16x2(q1, bh1, bl1);
                mma_bf16(acc[nt], ah[0], ah[1], ah[2], ah[3], bl0, bl1);
                mma_bf16(acc[nt], al[0], al[1], al[2], al[3], bh0, bh1);
                mma_bf16(acc[nt], ah[0], ah[1], ah[2], ah[3], bh0, bh1);
            }
        }
        __syncthreads();
        if (kt + STAGES - 1 < nk) load_stage(nxt, kt + STAGES - 1);
        else cp_commit();
        cur = (cur + 1 == STAGES) ? 0 : cur + 1;
        nxt = (nxt + 1 == STAGES) ? 0 : nxt + 1;
    }

#pragma unroll
    for (int nt = 0; nt < 4; nt++) {
        int col = wn + nt * 8 + 2 * tg;
        int row0 = wm + g;
        int row1 = row0 + 8;
#pragma unroll
        for (int cc = 0; cc < 2; cc++) {
            int gn = n0 + col + cc;
            if (gn < N) {
                C[(size_t)row0 * N + gn] = acc[nt][cc];
                C[(size_t)row1 * N + gn] = acc[nt][2 + cc];
            }
        }
    }
}

// ---------------- wide Wo GEMM: logits = tanh(y @ Wo^T + bo) + LSE partials -
// TILE 64x128, 3-stage cp.async, raw-fp32-bits fed as TF32 (no cvt).
// Epilogue also reduces per-CTA sum(exp(logit)) per batch row into g_lsepart
// (exact: logits in [-1,1], so unshifted sum-exp is overflow-safe).
__global__ __launch_bounds__(256) void gemm_wo_kernel(
        const float* __restrict__ X,    // [64, 2048]
        const float* __restrict__ W,    // [V, 2048]
        const float* __restrict__ bias, // [V]
        float* __restrict__ C) {        // [64, V]
    extern __shared__ float smem[];
    float* Abase = smem;                                  // [3][64][36]
    float* Bbase = smem + WO_STAGES * WO_A_FLOATS;        // [3][128][36]
    __shared__ float s_sum[64][2];

    const int tid = threadIdx.x;
    const int n0 = blockIdx.x * 128;
    const int warp = tid >> 5, lane = tid & 31;
    const int wm = (warp & 3) * 16;
    const int wngrp = warp >> 2;
    const int wn = wngrp * 64;
    const int g = lane >> 2, tg = lane & 3;

    const int K = 2 * HH;
    const int nk = K >> 5;       // 64

    auto load_stage = [&](int s, int kt) {
        int k0 = kt << 5;
        float* As = Abase + s * WO_A_FLOATS;
        float* Bs = Bbase + s * WO_B_FLOATS;
#pragma unroll
        for (int i = 0; i < 2; i++) {
            int c = tid + i * 256;
            int m = c >> 3, cc = c & 7;
            cp_async16(As + m * 36 + cc * 4, X + (size_t)m * K + k0 + cc * 4);
        }
#pragma unroll
        for (int i = 0; i < 4; i++) {
            int c = tid + i * 256;
            int n = c >> 3, cc = c & 7;
            int gn = n0 + n;
            cp_async16_z(Bs + n * 36 + cc * 4, W + (size_t)gn * K + k0 + cc * 4, gn < VV);
        }
        cp_commit();
    };

    float acc[8][4];
#pragma unroll
    for (int i = 0; i < 8; i++)
#pragma unroll
        for (int j = 0; j < 4; j++) acc[i][j] = 0.f;

    load_stage(0, 0);
    load_stage(1, 1);

    int cur = 0, nxt = 2;
    for (int kt = 0; kt < nk; kt++) {
        cp_wait<1>();
        __syncthreads();
        const float* As = Abase + cur * WO_A_FLOATS;
        const float* Bs = Bbase + cur * WO_B_FLOATS;

#pragma unroll
        for (int ks = 0; ks < 4; ks++) {
            uint32_t a0 = __float_as_uint(As[(wm + g) * 36 + ks * 8 + tg]);
            uint32_t a1 = __float_as_uint(As[(wm + g + 8) * 36 + ks * 8 + tg]);
            uint32_t a2 = __float_as_uint(As[(wm + g) * 36 + ks * 8 + tg + 4]);
            uint32_t a3 = __float_as_uint(As[(wm + g + 8) * 36 + ks * 8 + tg + 4]);
#pragma unroll
            for (int nt = 0; nt < 8; nt++) {
                uint32_t b0 = __float_as_uint(Bs[(wn + nt * 8 + g) * 36 + ks * 8 + tg]);
                uint32_t b1 = __float_as_uint(Bs[(wn + nt * 8 + g) * 36 + ks * 8 + tg + 4]);
                mma_tf32(acc[nt], a0, a1, a2, a3, b0, b1);
            }
        }
        __syncthreads();
        if (kt + 2 < nk) load_stage(nxt, kt + 2);
        else cp_commit();
        cur = (cur == 2) ? 0 : cur + 1;
        nxt = (nxt == 2) ? 0 : nxt + 1;
    }

    float ps0 = 0.f, ps1 = 0.f;
#pragma unroll
    for (int nt = 0; nt < 8; nt++) {
        int col = wn + nt * 8 + 2 * tg;
        int row0 = wm + g;
        int row1 = row0 + 8;
#pragma unroll
        for (int cc = 0; cc < 2; cc++) {
            int gn = n0 + col + cc;
            if (gn < VV) {
                float bv = bias[gn];
                float v0 = tanhf(acc[nt][cc] + bv);
                float v1 = tanhf(acc[nt][2 + cc] + bv);
                C[(size_t)row0 * VV + gn] = v0;
                C[(size_t)row1 * VV + gn] = v1;
                ps0 += __expf(v0);
                ps1 += __expf(v1);
            }
        }
    }
    // reduce across the 4 tg lanes of each quad (same row)
    ps0 += __shfl_xor_sync(0xffffffffu, ps0, 1);
    ps0 += __shfl_xor_sync(0xffffffffu, ps0, 2);
    ps1 += __shfl_xor_sync(0xffffffffu, ps1, 1);
    ps1 += __shfl_xor_sync(0xffffffffu, ps1, 2);
    if (tg == 0) {
        s_sum[wm + g][wngrp] = ps0;
        s_sum[wm + g + 8][wngrp] = ps1;
    }
    __syncthreads();
    if (tid < 64)
        g_lsepart[(size_t)blockIdx.x * BB + tid] = s_sum[tid][0] + s_sum[tid][1];
}

// ---------------- combine LSE partials: lse[b] = log(sum over blocks) -------
__global__ __launch_bounds__(128) void lse_combine_kernel() {
    int b = blockIdx.x;
    int tid = threadIdx.x;
    float s = 0.f;
    for (int c = tid; c < NWO; c += 128)
        s += g_lsepart[(size_t)c * BB + b];
#pragma unroll
    for (int o = 16; o; o >>= 1) s += __shfl_xor_sync(0xffffffffu, s, o);
    __shared__ float ws[4];
    if ((tid & 31) == 0) ws[tid >> 5] = s;
    __syncthreads();
    if (tid == 0)
        g_lse[b] = logf(ws[0] + ws[1] + ws[2] + ws[3]);
}

// ---------------- GRU gates (fused: h_new, new_hidden, optional y) ---------
__global__ __launch_bounds__(256) void gru_gates_kernel(
        const float* __restrict__ giA, const float* __restrict__ giB,
        const float* __restrict__ bi,
        const float* __restrict__ gh, const float* __restrict__ bh,
        const float* __restrict__ hprev, float* __restrict__ hnew,
        float* __restrict__ hid_dst,
        float* __restrict__ y_dst) {
    int idx = blockIdx.x * blockDim.x + threadIdx.x;  // B*H
    int b = idx >> 10;
    int h = idx & 1023;
    size_t base = (size_t)b * 3 * HH;
    float ir = giA[base + h]           + giB[base + h]           + bi[h];
    float iz = giA[base + HH + h]      + giB[base + HH + h]      + bi[HH + h];
    float in_ = giA[base + 2 * HH + h] + giB[base + 2 * HH + h]  + bi[2 * HH + h];
    float hr = gh[base + h]           + bh[h];
    float hz = gh[base + HH + h]      + bh[HH + h];
    float hn = gh[base + 2 * HH + h]  + bh[2 * HH + h];
    float r = 1.f / (1.f + __expf(-(ir + hr)));
    float z = 1.f / (1.f + __expf(-(iz + hz)));
    float n = tanhf(in_ + r * hn);
    float v = (1.f - z) * n + z * hprev[idx];
    hnew[idx] = v;
    hid_dst[idx] = v + g_x[b * 2 * HH + h];
    if (y_dst) y_dst[b * 2 * HH + h] = v;
}

// ---------------- attention partial (flash pass) ----------------
__global__ __launch_bounds__(128) void attn_partial_kernel(const float* __restrict__ enc) {
    const int b = blockIdx.y;
    const int warp = threadIdx.x >> 5, lane = threadIdx.x & 31;
    const int seg = blockIdx.x * 4 + warp;
    const size_t tstride = (size_t)BB * HH;

    float4 uu[8];
#pragma unroll
    for (int i = 0; i < 8; i++) {
        int off = b * HH + i * 128 + lane * 4;
        float4 u0 = *(const float4*)&g_up[off];
        float4 u1 = *(const float4*)&g_up[BB * HH + off];
        float4 u2 = *(const float4*)&g_up[2 * BB * HH + off];
        float4 u3 = *(const float4*)&g_up[3 * BB * HH + off];
        uu[i].x = u0.x + u1.x + u2.x + u3.x;
        uu[i].y = u0.y + u1.y + u2.y + u3.y;
        uu[i].z = u0.z + u1.z + u2.z + u3.z;
        uu[i].w = u0.w + u1.w + u2.w + u3.w;
    }

    float4 cc[8];
#pragma unroll
    for (int i = 0; i < 8; i++) cc[i] = make_float4(0.f, 0.f, 0.f, 0.f);

    float m = -1e30f, l = 0.f;
    const int t0 = seg * 32;
    const float* ep = enc + ((size_t)t0 * BB + b) * HH;

    float4 eA[8], eB[8];
#pragma unroll
    for (int i = 0; i < 8; i++)
        eA[i] = *(const float4*)&ep[i * 128 + lane * 4];

    auto process = [&](const float4 (&e)[8], int t) {
        float d = 0.f;
#pragma unroll
        for (int i = 0; i < 8; i++) {
            d += e[i].x * uu[i].x + e[i].y * uu[i].y +
                 e[i].z * uu[i].z + e[i].w * uu[i].w;
        }
#pragma unroll
        for (int o = 16; o; o >>= 1) d += __shfl_xor_sync(0xffffffffu, d, o);
        if (lane == 0) g_scores[b * TT + t] = d;
        float mn = fmaxf(m, d);
        float corr = __expf(m - mn);
        float p = __expf(d - mn);
        l = l * corr + p;
        m = mn;
#pragma unroll
        for (int i = 0; i < 8; i++) {
            cc[i].x = cc[i].x * corr + p * e[i].x;
            cc[i].y = cc[i].y * corr + p * e[i].y;
            cc[i].z = cc[i].z * corr + p * e[i].z;
            cc[i].w = cc[i].w * corr + p * e[i].w;
        }
    };

    for (int tt = 0; tt < 32; tt += 2) {
        const float* ep1 = ep + tstride;
#pragma unroll
        for (int i = 0; i < 8; i++)
            eB[i] = *(const float4*)&ep1[i * 128 + lane * 4];
        process(eA, t0 + tt);
        const float* ep2 = ep + 2 * tstride;
        if (tt + 2 < 32) {
#pragma unroll
            for (int i = 0; i < 8; i++)
                eA[i] = *(const float4*)&ep2[i * 128 + lane * 4];
        }
        process(eB, t0 + tt + 1);
        ep = ep2;
    }

    float* cp = &g_ctxpart[((size_t)b * 64 + seg) * HH];
#pragma unroll
    for (int i = 0; i < 8; i++)
        *(float4*)&cp[i * 128 + lane * 4] = cc[i];
    if (lane == 0) {
        g_mpart[b * 64 + seg] = m;
        g_lpart[b * 64 + seg] = l;
    }
}

// ---------------- combine partials -> context, y, attn probs ----------------
__global__ __launch_bounds__(256) void attn_combine_kernel(
        float* __restrict__ ctx_out, float* __restrict__ attn_out) {
    int b = blockIdx.x;
    int tid = threadIdx.x;
    __shared__ float sm[64], sl[64], sw[64];
    __shared__ float sML[2];
    if (tid < 64) {
        sm[tid] = g_mpart[b * 64 + tid];
        sl[tid] = g_lpart[b * 64 + tid];
    }
    __syncthreads();
    if (tid == 0) {
        float M = -1e30f;
        for (int s = 0; s < 64; s++) M = fmaxf(M, sm[s]);
        float L = 0.f;
        for (int s = 0; s < 64; s++) L += sl[s] * __expf(sm[s] - M);
        sML[0] = M; sML[1] = L;
    }
    __syncthreads();
    if (tid < 64) sw[tid] = __expf(sm[tid] - sML[0]) / sML[1];
    __syncthreads();

    int h = tid * 4;
    float4 a = make_float4(0.f, 0.f, 0.f, 0.f);
    for (int s = 0; s < 64; s++) {
        float4 v = *(const float4*)&g_ctxpart[((size_t)b * 64 + s) * HH + h];
        float w = sw[s];
        a.x += w * v.x; a.y += w * v.y; a.z += w * v.z; a.w += w * v.w;
    }
    *(float4*)&ctx_out[b * HH + h] = a;
    *(float4*)&g_y[b * 2 * HH + HH + h] = a;

    const float M = sML[0], L = sML[1];
    for (int t = tid; t < TT; t += 256)
        attn_out[b * TT + t] = __expf(g_scores[b * TT + t] - M) / L;
}

// ---------------- out = logits - lse ----------------
__global__ __launch_bounds__(256) void out_write_kernel(float* __restrict__ out) {
    int idx = blockIdx.x * blockDim.x + threadIdx.x;
    if (idx >= BB * VV) return;
    int b = idx / VV;
    out[idx] = g_logits[idx] - g_lse[b];
}

// ---------------- launch ----------------
extern "C" void kernel_launch(void* const* d_in, const int* in_sizes, int n_in,
                              void* d_out, int out_size) {
    const int*   inputs  = (const int*)d_in[0];
    const float* hidden  = (const float*)d_in[1];
    const float* context = (const float*)d_in[2];
    const float* enc     = (const float*)d_in[3];
    const float* E       = (const float*)d_in[4];
    const float* W_ih0   = (const float*)d_in[5];
    const float* W_hh0   = (const float*)d_in[6];
    const float* b_ih0   = (const float*)d_in[7];
    const float* b_hh0   = (const float*)d_in[8];
    const float* W_ih1   = (const float*)d_in[9];
    const float* W_hh1   = (const float*)d_in[10];
    const float* b_ih1   = (const float*)d_in[11];
    const float* b_hh1   = (const float*)d_in[12];
    const float* Wa      = (const float*)d_in[13];
    // d_in[14] = ba: softmax-invariant per-batch constant -> unused
    const float* Wo      = (const float*)d_in[15];
    const float* bo      = (const float*)d_in[16];

    float* out0     = (float*)d_out;
    float* hid_out  = out0 + (size_t)BB * VV;
    float* ctx_out  = hid_out + 2 * BB * HH;
    float* attn_out = ctx_out + BB * HH;

    void *p_x, *p_gi, *p_gia, *p_gh, *p_gh1, *p_h0, *p_h1, *p_up, *p_y, *p_logits;
    cudaGetSymbolAddress(&p_x, g_x);
    cudaGetSymbolAddress(&p_gi, g_gi);
    cudaGetSymbolAddress(&p_gia, g_gia);
    cudaGetSymbolAddress(&p_gh, g_gh);
    cudaGetSymbolAddress(&p_gh1, g_gh1);
    cudaGetSymbolAddress(&p_h0, g_h0);
    cudaGetSymbolAddress(&p_h1, g_h1);
    cudaGetSymbolAddress(&p_up, g_up);
    cudaGetSymbolAddress(&p_y, g_y);
    cudaGetSymbolAddress(&p_logits, g_logits);
    float* xx  = (float*)p_x;
    float* gi  = (float*)p_gi;
    float* gia = (float*)p_gia;
    float* gh  = (float*)p_gh;
    float* gh1 = (float*)p_gh1;
    float* h0  = (float*)p_h0;
    float* h1  = (float*)p_h1;
    float* up  = (float*)p_up;
    float* yy  = (float*)p_y;
    float* lg  = (float*)p_logits;

    static bool attr_done = false;
    if (!attr_done) {
        cudaFuncSetAttribute(gemm_multi_kernel<false>,
                             cudaFuncAttributeMaxDynamicSharedMemorySize, GEMM_SMEM_BYTES);
        cudaFuncSetAttribute(gemm_multi_kernel<true>,
                             cudaFuncAttributeMaxDynamicSharedMemorySize, GEMM_SMEM_BYTES);
        cudaFuncSetAttribute(gemm_wo_kernel,
                             cudaFuncAttributeMaxDynamicSharedMemorySize, WO_SMEM_BYTES);
        attr_done = true;
    }

    // 1) x = concat(E[inputs], context)
    build_x_kernel<<<(BB * 2 * HH) / 256, 256>>>(inputs, E, context);

    // 2) G1: gi0 split-K (emb half, ctx half), gh0, gh1 — one launch, grid 192
    {
        Probs4 P;
        P.p[0] = { xx,            W_ih0,        gi,  2 * HH, 2 * HH, 3 * HH, HH };
        P.p[1] = { xx + HH,       W_ih0 + HH,   gia, 2 * HH, 2 * HH, 3 * HH, HH };
        P.p[2] = { hidden,        W_hh0,        gh,  HH,     HH,     3 * HH, HH };
        P.p[3] = { hidden + BB * HH, W_hh1,     gh1, HH,     HH,     3 * HH, HH };
        gemm_multi_kernel<false><<<dim3(48, 4), 256, GEMM_SMEM_BYTES>>>(P);
    }
    gru_gates_kernel<<<(BB * HH) / 256, 256>>>(gi, gia, b_ih0, gh, b_hh0,
                                               hidden, h0, hid_out, nullptr);

    // 3) G2: gi1 split-K=2 — grid 96
    {
        Probs4 P;
        P.p[0] = { h0,                 W_ih1,              gi,  HH, HH, 3 * HH, HH / 2 };
        P.p[1] = { h0 + HH / 2,        W_ih1 + HH / 2,     gia, HH, HH, 3 * HH, HH / 2 };
        P.p[2] = P.p[0]; P.p[3] = P.p[0];
        gemm_multi_kernel<false><<<dim3(48, 2), 256, GEMM_SMEM_BYTES>>>(P);
    }
    gru_gates_kernel<<<(BB * HH) / 256, 256>>>(gi, gia, b_ih1, gh1, b_hh1,
                                               hidden + BB * HH, h1,
                                               hid_out + BB * HH, yy);

    // 4) u = h1 @ Wa, split-K=4 — grid 64 (Wa is [K,N] -> TRANS)
    {
        Probs4 P;
        P.p[0] = { h1,            Wa,                       up,               HH, HH, HH, HH / 4 };
        P.p[1] = { h1 + 256,      Wa + (size_t)256 * HH,    up + BB * HH,     HH, HH, HH, HH / 4 };
        P.p[2] = { h1 + 512,      Wa + (size_t)512 * HH,    up + 2 * BB * HH, HH, HH, HH, HH / 4 };
        P.p[3] = { h1 + 768,      Wa + (size_t)768 * HH,    up + 3 * BB * HH, HH, HH, HH, HH / 4 };
        gemm_multi_kernel<true><<<dim3(16, 4), 256, GEMM_SMEM_BYTES>>>(P);
    }

    // 5) flash-attention pass + fused combine/attn-prob write
    attn_partial_kernel<<<dim3(16, BB), 128>>>(enc);
    attn_combine_kernel<<<BB, 256>>>(ctx_out, attn_out);

    // 6) logits = tanh(y @ Wo^T + bo), fused LSE partials — grid 393
    gemm_wo_kernel<<<NWO, 256, WO_SMEM_BYTES>>>(yy, Wo, bo, lg);

    // 7) log_softmax epilogue
    lse_combine_kernel<<<BB, 128>>>();
    out_write_kernel<<<(BB * VV + 255) / 256, 256>>>(out0);
}

// round 12
// speedup vs baseline: 4.2257x; 1.0127x over previous
#include <cuda_runtime.h>
#include <cstdint>
#include <cstddef>

#define HH 1024
#define VV 50257
#define BB 64
#define TT 2048

#define STAGES 6
#define STAGE_FLOATS 2304                    // A: 64*36; B: max(64*36, 32*68)
#define GEMM_SMEM_BYTES (STAGES * 2 * STAGE_FLOATS * 4)   // 110592

#define WO_STAGES 3
#define WO_A_FLOATS 2304                     // 64*36
#define WO_B_FLOATS 4608                     // 128*36
#define WO_SMEM_BYTES (WO_STAGES * (WO_A_FLOATS + WO_B_FLOATS) * 4)  // 82944
#define NWO ((VV + 127) / 128)               // 393 Wo blocks

// ---------------- scratch (device globals: no allocation) ----------------
__device__ float g_x[BB * 2 * HH];          // [B,2H] concat(embedded, context)
__device__ float g_gi[BB * 3 * HH];         // gi partials (4)
__device__ float g_gia[BB * 3 * HH];
__device__ float g_gib[BB * 3 * HH];
__device__ float g_gic[BB * 3 * HH];
__device__ float g_gh[BB * 3 * HH];         // gh layer-0 partials (2)
__device__ float g_gha[BB * 3 * HH];
__device__ float g_gh1[BB * 3 * HH];        // gh layer-1 partials (2)
__device__ float g_gh1a[BB * 3 * HH];
__device__ float g_h0[BB * HH];
__device__ float g_h1[BB * HH];
__device__ float g_up[8 * BB * HH];         // u split-K partials
__device__ float g_u[BB * HH];              // reduced u
__device__ float g_scores[BB * TT];
__device__ float g_ctxpart[(size_t)BB * 64 * HH];
__device__ float g_mpart[BB * 64];
__device__ float g_lpart[BB * 64];
__device__ float g_y[BB * 2 * HH];          // [B,2H] concat(output, context)
__device__ float g_logits[(size_t)BB * VV];
__device__ float g_lsepart[(size_t)NWO * BB];
__device__ float g_lse[BB];

// ---------------- helpers ----------------
// split float2 -> packed bf16x2 (hi, lo) pair; low half = .x (lower k index)
__device__ __forceinline__ void split_bf16x2(float2 p, uint32_t& hi, uint32_t& lo) {
    asm("cvt.rn.bf16x2.f32 %0, %1, %2;" : "=r"(hi) : "f"(p.y), "f"(p.x));
    float h0 = __uint_as_float(hi << 16);
    float h1 = __uint_as_float(hi & 0xffff0000u);
    float r0 = p.x - h0;
    float r1 = p.y - h1;
    asm("cvt.rn.bf16x2.f32 %0, %1, %2;" : "=r"(lo) : "f"(r1), "f"(r0));
}

__device__ __forceinline__ void mma_bf16(float c[4], uint32_t a0, uint32_t a1,
                                         uint32_t a2, uint32_t a3,
                                         uint32_t b0, uint32_t b1) {
    asm volatile(
        "mma.sync.aligned.m16n8k16.row.col.f32.bf16.bf16.f32 "
        "{%0,%1,%2,%3}, {%4,%5,%6,%7}, {%8,%9}, {%0,%1,%2,%3};"
        : "+f"(c[0]), "+f"(c[1]), "+f"(c[2]), "+f"(c[3])
        : "r"(a0), "r"(a1), "r"(a2), "r"(a3), "r"(b0), "r"(b1));
}

__device__ __forceinline__ void mma_tf32(float c[4], uint32_t a0, uint32_t a1,
                                         uint32_t a2, uint32_t a3,
                                         uint32_t b0, uint32_t b1) {
    asm volatile(
        "mma.sync.aligned.m16n8k8.row.col.f32.tf32.tf32.f32 "
        "{%0,%1,%2,%3}, {%4,%5,%6,%7}, {%8,%9}, {%0,%1,%2,%3};"
        : "+f"(c[0]), "+f"(c[1]), "+f"(c[2]), "+f"(c[3])
        : "r"(a0), "r"(a1), "r"(a2), "r"(a3), "r"(b0), "r"(b1));
}

__device__ __forceinline__ void cp_async16(float* dst, const float* src) {
    uint32_t s = (uint32_t)__cvta_generic_to_shared(dst);
    asm volatile("cp.async.cg.shared.global [%0], [%1], 16;" :: "r"(s), "l"(src));
}
__device__ __forceinline__ void cp_async16_z(float* dst, const float* src, bool valid) {
    uint32_t s = (uint32_t)__cvta_generic_to_shared(dst);
    int sz = valid ? 16 : 0;
    asm volatile("cp.async.cg.shared.global [%0], [%1], 16, %2;" :: "r"(s), "l"(src), "r"(sz));
}
__device__ __forceinline__ void cp_commit() { asm volatile("cp.async.commit_group;"); }
template <int N>
__device__ __forceinline__ void cp_wait() { asm volatile("cp.async.wait_group %0;" :: "n"(N)); }

// ---------------- K1: x = concat(E[inputs], context) ----------------
__global__ __launch_bounds__(256) void build_x_kernel(
        const int* __restrict__ inputs,
        const float* __restrict__ E,
        const float* __restrict__ context) {
    int idx = blockIdx.x * blockDim.x + threadIdx.x;
    int b = idx >> 11;
    int j = idx & 2047;
    float v;
    if (j < HH) v = E[(size_t)inputs[b] * HH + j];
    else        v = context[b * HH + (j - HH)];
    g_x[idx] = v;
}

// ---------------- multi-problem precise (3xBF16) 64xN GEMM ----------------
struct Prob {
    const float* X;   // [64, k] rows with stride xs
    const float* W;   // TRANS=0: [n, k] stride ws; TRANS=1: [k, n] stride ws
    float* C;         // [64, n] stride n
    int xs, ws, n, k;
};
struct Probs8 { Prob p[8]; };

template <bool TRANS>
__global__ __launch_bounds__(256) void gemm_multi_kernel(Probs8 P) {
    const Prob pr = P.p[blockIdx.y];
    const float* __restrict__ X = pr.X;
    const float* __restrict__ W = pr.W;
    float* __restrict__ C = pr.C;
    const int xs = pr.xs, ws = pr.ws, N = pr.n, K = pr.k;

    extern __shared__ float smem[];
    float* Abase = smem;
    float* Bbase = smem + STAGES * STAGE_FLOATS;

    const int tid = threadIdx.x;
    const int n0 = blockIdx.x * 64;
    const int warp = tid >> 5, lane = tid & 31;
    const int wm = (warp & 3) * 16;
    const int wn = (warp >> 2) * 32;
    const int g = lane >> 2, tg = lane & 3;

    const int nk = K >> 5;

    auto load_stage = [&](int s, int kt) {
        int k0 = kt << 5;
        float* As = Abase + s * STAGE_FLOATS;
        float* Bs = Bbase + s * STAGE_FLOATS;
#pragma unroll
        for (int i = 0; i < 2; i++) {
            int c = tid + i * 256;
            int m = c >> 3, cc = c & 7;
            cp_async16(As + m * 36 + cc * 4, X + (size_t)m * xs + k0 + cc * 4);
        }
        if (!TRANS) {
#pragma unroll
            for (int i = 0; i < 2; i++) {
                int c = tid + i * 256;
                int n = c >> 3, cc = c & 7;
                int gn = n0 + n;
                cp_async16_z(Bs + n * 36 + cc * 4, W + (size_t)gn * ws + k0 + cc * 4, gn < N);
            }
        } else {
#pragma unroll
            for (int i = 0; i < 2; i++) {
                int c = tid + i * 256;
                int kk = c >> 4, cc = c & 15;
                int gn = n0 + cc * 4;
                cp_async16_z(Bs + kk * 68 + cc * 4, W + (size_t)(k0 + kk) * ws + gn, gn < N);
            }
        }
        cp_commit();
    };

    float acc[4][4];
#pragma unroll
    for (int i = 0; i < 4; i++)
#pragma unroll
        for (int j = 0; j < 4; j++) acc[i][j] = 0.f;

    // prologue (guarded: nk may be < STAGES-1)
    for (int s = 0; s < STAGES - 1; s++) {
        if (s < nk) load_stage(s, s);
        else cp_commit();
    }

    int cur = 0, nxt = STAGES - 1;   // wrap counters (STAGES not power of 2)
    for (int kt = 0; kt < nk; kt++) {
        cp_wait<STAGES - 2>();
        __syncthreads();
        const float* As = Abase + cur * STAGE_FLOATS;
        const float* Bs = Bbase + cur * STAGE_FLOATS;

#pragma unroll
        for (int ks2 = 0; ks2 < 2; ks2++) {
            const int kb = ks2 * 16;
            uint32_t ah[4], al[4];
            {
                float2 p;
                p = *(const float2*)&As[(wm + g) * 36 + kb + 2 * tg];
                split_bf16x2(p, ah[0], al[0]);
                p = *(const float2*)&As[(wm + g + 8) * 36 + kb + 2 * tg];
                split_bf16x2(p, ah[1], al[1]);
                p = *(const float2*)&As[(wm + g) * 36 + kb + 8 + 2 * tg];
                split_bf16x2(p, ah[2], al[2]);
                p = *(const float2*)&As[(wm + g + 8) * 36 + kb + 8 + 2 * tg];
                split_bf16x2(p, ah[3], al[3]);
            }
#pragma unroll
            for (int nt = 0; nt < 4; nt++) {
                float2 q0, q1;
                if (!TRANS) {
                    int n = wn + nt * 8 + g;
                    q0 = *(const float2*)&Bs[n * 36 + kb + 2 * tg];
                    q1 = *(const float2*)&Bs[n * 36 + kb + 8 + 2 * tg];
                } else {
                    int n = wn + nt * 8 + g;
                    q0.x = Bs[(kb + 2 * tg) * 68 + n];
                    q0.y = Bs[(kb + 2 * tg + 1) * 68 + n];
                    q1.x = Bs[(kb + 8 + 2 * tg) * 68 + n];
                    q1.y = Bs[(kb + 9 + 2 * tg) * 68 + n];
                }
                uint32_t bh0, bl0, bh1, bl1;
                split_bf16x2(q0, bh0, bl0);
                split_bf16x2(q1, bh1, bl1);
                mma_bf16(acc[nt], ah[0], ah[1], ah[2], ah[3], bl0, bl1);
                mma_bf16(acc[nt], al[0], al[1], al[2], al[3], bh0, bh1);
                mma_bf16(acc[nt], ah[0], ah[1], ah[2], ah[3], bh0, bh1);
            }
        }
        __syncthreads();
        if (kt + STAGES - 1 < nk) load_stage(nxt, kt + STAGES - 1);
        else cp_commit();
        cur = (cur + 1 == STAGES) ? 0 : cur + 1;
        nxt = (nxt + 1 == STAGES) ? 0 : nxt + 1;
    }

#pragma unroll
    for (int nt = 0; nt < 4; nt++) {
        int col = wn + nt * 8 + 2 * tg;
        int row0 = wm + g;
        int row1 = row0 + 8;
#pragma unroll
        for (int cc = 0; cc < 2; cc++) {
            int gn = n0 + col + cc;
            if (gn < N) {
                C[(size_t)row0 * N + gn] = acc[nt][cc];
                C[(size_t)row1 * N + gn] = acc[nt][2 + cc];
            }
        }
    }
}

// ---------------- wide Wo GEMM: logits = tanh(y @ Wo^T + bo) + LSE partials -
__global__ __launch_bounds__(256) void gemm_wo_kernel(
        const float* __restrict__ X,    // [64, 2048]
        const float* __restrict__ W,    // [V, 2048]
        const float* __restrict__ bias, // [V]
        float* __restrict__ C) {        // [64, V]
    extern __shared__ float smem[];
    float* Abase = smem;                                  // [3][64][36]
    float* Bbase = smem + WO_STAGES * WO_A_FLOATS;        // [3][128][36]
    __shared__ float s_sum[64][2];

    const int tid = threadIdx.x;
    const int n0 = blockIdx.x * 128;
    const int warp = tid >> 5, lane = tid & 31;
    const int wm = (warp & 3) * 16;
    const int wngrp = warp >> 2;
    const int wn = wngrp * 64;
    const int g = lane >> 2, tg = lane & 3;

    const int K = 2 * HH;
    const int nk = K >> 5;       // 64

    auto load_stage = [&](int s, int kt) {
        int k0 = kt << 5;
        float* As = Abase + s * WO_A_FLOATS;
        float* Bs = Bbase + s * WO_B_FLOATS;
#pragma unroll
        for (int i = 0; i < 2; i++) {
            int c = tid + i * 256;
            int m = c >> 3, cc = c & 7;
            cp_async16(As + m * 36 + cc * 4, X + (size_t)m * K + k0 + cc * 4);
        }
#pragma unroll
        for (int i = 0; i < 4; i++) {
            int c = tid + i * 256;
            int n = c >> 3, cc = c & 7;
            int gn = n0 + n;
            cp_async16_z(Bs + n * 36 + cc * 4, W + (size_t)gn * K + k0 + cc * 4, gn < VV);
        }
        cp_commit();
    };

    float acc[8][4];
#pragma unroll
    for (int i = 0; i < 8; i++)
#pragma unroll
        for (int j = 0; j < 4; j++) acc[i][j] = 0.f;

    load_stage(0, 0);
    load_stage(1, 1);

    int cur = 0, nxt = 2;
    for (int kt = 0; kt < nk; kt++) {
        cp_wait<1>();
        __syncthreads();
        const float* As = Abase + cur * WO_A_FLOATS;
        const float* Bs = Bbase + cur * WO_B_FLOATS;

#pragma unroll
        for (int ks = 0; ks < 4; ks++) {
            uint32_t a0 = __float_as_uint(As[(wm + g) * 36 + ks * 8 + tg]);
            uint32_t a1 = __float_as_uint(As[(wm + g + 8) * 36 + ks * 8 + tg]);
            uint32_t a2 = __float_as_uint(As[(wm + g) * 36 + ks * 8 + tg + 4]);
            uint32_t a3 = __float_as_uint(As[(wm + g + 8) * 36 + ks * 8 + tg + 4]);
#pragma unroll
            for (int nt = 0; nt < 8; nt++) {
                uint32_t b0 = __float_as_uint(Bs[(wn + nt * 8 + g) * 36 + ks * 8 + tg]);
                uint32_t b1 = __float_as_uint(Bs[(wn + nt * 8 + g) * 36 + ks * 8 + tg + 4]);
                mma_tf32(acc[nt], a0, a1, a2, a3, b0, b1);
            }
        }
        __syncthreads();
        if (kt + 2 < nk) load_stage(nxt, kt + 2);
        else cp_commit();
        cur = (cur == 2) ? 0 : cur + 1;
        nxt = (nxt == 2) ? 0 : nxt + 1;
    }

    float ps0 = 0.f, ps1 = 0.f;
#pragma unroll
    for (int nt = 0; nt < 8; nt++) {
        int col = wn + nt * 8 + 2 * tg;
        int row0 = wm + g;
        int row1 = row0 + 8;
#pragma unroll
        for (int cc = 0; cc < 2; cc++) {
            int gn = n0 + col + cc;
            if (gn < VV) {
                float bv = bias[gn];
                float v0 = tanhf(acc[nt][cc] + bv);
                float v1 = tanhf(acc[nt][2 + cc] + bv);
                C[(size_t)row0 * VV + gn] = v0;
                C[(size_t)row1 * VV + gn] = v1;
                ps0 += __expf(v0);
                ps1 += __expf(v1);
            }
        }
    }
    ps0 += __shfl_xor_sync(0xffffffffu, ps0, 1);
    ps0 += __shfl_xor_sync(0xffffffffu, ps0, 2);
    ps1 += __shfl_xor_sync(0xffffffffu, ps1, 1);
    ps1 += __shfl_xor_sync(0xffffffffu, ps1, 2);
    if (tg == 0) {
        s_sum[wm + g][wngrp] = ps0;
        s_sum[wm + g + 8][wngrp] = ps1;
    }
    __syncthreads();
    if (tid < 64)
        g_lsepart[(size_t)blockIdx.x * BB + tid] = s_sum[tid][0] + s_sum[tid][1];
}

// ---------------- combine LSE partials ----------------
__global__ __launch_bounds__(128) void lse_combine_kernel() {
    int b = blockIdx.x;
    int tid = threadIdx.x;
    float s = 0.f;
    for (int c = tid; c < NWO; c += 128)
        s += g_lsepart[(size_t)c * BB + b];
#pragma unroll
    for (int o = 16; o; o >>= 1) s += __shfl_xor_sync(0xffffffffu, s, o);
    __shared__ float ws[4];
    if ((tid & 31) == 0) ws[tid >> 5] = s;
    __syncthreads();
    if (tid == 0)
        g_lse[b] = logf(ws[0] + ws[1] + ws[2] + ws[3]);
}

// ---------------- GRU gates (sums 4 gi + 2 gh partials; fused outputs) ------
__global__ __launch_bounds__(256) void gru_gates_kernel(
        const float* __restrict__ gi0, const float* __restrict__ gi1,
        const float* __restrict__ gi2, const float* __restrict__ gi3,
        const float* __restrict__ bi,
        const float* __restrict__ gh0, const float* __restrict__ gh1p,
        const float* __restrict__ bh,
        const float* __restrict__ hprev, float* __restrict__ hnew,
        float* __restrict__ hid_dst,
        float* __restrict__ y_dst) {
    int idx = blockIdx.x * blockDim.x + threadIdx.x;  // B*H
    int b = idx >> 10;
    int h = idx & 1023;
    size_t base = (size_t)b * 3 * HH;
    float ir = gi0[base + h] + gi1[base + h] + gi2[base + h] + gi3[base + h] + bi[h];
    float iz = gi0[base + HH + h] + gi1[base + HH + h] + gi2[base + HH + h] + gi3[base + HH + h] + bi[HH + h];
    float in_ = gi0[base + 2 * HH + h] + gi1[base + 2 * HH + h] + gi2[base + 2 * HH + h] + gi3[base + 2 * HH + h] + bi[2 * HH + h];
    float hr = gh0[base + h]          + gh1p[base + h]          + bh[h];
    float hz = gh0[base + HH + h]     + gh1p[base + HH + h]     + bh[HH + h];
    float hn = gh0[base + 2 * HH + h] + gh1p[base + 2 * HH + h] + bh[2 * HH + h];
    float r = 1.f / (1.f + __expf(-(ir + hr)));
    float z = 1.f / (1.f + __expf(-(iz + hz)));
    float n = tanhf(in_ + r * hn);
    float v = (1.f - z) * n + z * hprev[idx];
    hnew[idx] = v;
    hid_dst[idx] = v + g_x[b * 2 * HH + h];
    if (y_dst) y_dst[b * 2 * HH + h] = v;
}

// ---------------- reduce u partials: g_u = sum of 8 ----------------
__global__ __launch_bounds__(256) void u_reduce_kernel() {
    int idx = (blockIdx.x * blockDim.x + threadIdx.x) * 4;   // B*H/4 threads
    float4 a = *(const float4*)&g_up[idx];
#pragma unroll
    for (int p = 1; p < 8; p++) {
        float4 v = *(const float4*)&g_up[p * BB * HH + idx];
        a.x += v.x; a.y += v.y; a.z += v.z; a.w += v.w;
    }
    *(float4*)&g_u[idx] = a;
}

// ---------------- attention partial (flash pass) ----------------
__global__ __launch_bounds__(128) void attn_partial_kernel(const float* __restrict__ enc) {
    const int b = blockIdx.y;
    const int warp = threadIdx.x >> 5, lane = threadIdx.x & 31;
    const int seg = blockIdx.x * 4 + warp;
    const size_t tstride = (size_t)BB * HH;

    float4 uu[8];
#pragma unroll
    for (int i = 0; i < 8; i++)
        uu[i] = *(const float4*)&g_u[b * HH + i * 128 + lane * 4];

    float4 cc[8];
#pragma unroll
    for (int i = 0; i < 8; i++) cc[i] = make_float4(0.f, 0.f, 0.f, 0.f);

    float m = -1e30f, l = 0.f;
    const int t0 = seg * 32;
    const float* ep = enc + ((size_t)t0 * BB + b) * HH;

    float4 eA[8], eB[8];
#pragma unroll
    for (int i = 0; i < 8; i++)
        eA[i] = *(const float4*)&ep[i * 128 + lane * 4];

    auto process = [&](const float4 (&e)[8], int t) {
        float d = 0.f;
#pragma unroll
        for (int i = 0; i < 8; i++) {
            d += e[i].x * uu[i].x + e[i].y * uu[i].y +
                 e[i].z * uu[i].z + e[i].w * uu[i].w;
        }
#pragma unroll
        for (int o = 16; o; o >>= 1) d += __shfl_xor_sync(0xffffffffu, d, o);
        if (lane == 0) g_scores[b * TT + t] = d;
        float mn = fmaxf(m, d);
        float corr = __expf(m - mn);
        float p = __expf(d - mn);
        l = l * corr + p;
        m = mn;
#pragma unroll
        for (int i = 0; i < 8; i++) {
            cc[i].x = cc[i].x * corr + p * e[i].x;
            cc[i].y = cc[i].y * corr + p * e[i].y;
            cc[i].z = cc[i].z * corr + p * e[i].z;
            cc[i].w = cc[i].w * corr + p * e[i].w;
        }
    };

    for (int tt = 0; tt < 32; tt += 2) {
        const float* ep1 = ep + tstride;
#pragma unroll
        for (int i = 0; i < 8; i++)
            eB[i] = *(const float4*)&ep1[i * 128 + lane * 4];
        process(eA, t0 + tt);
        const float* ep2 = ep + 2 * tstride;
        if (tt + 2 < 32) {
#pragma unroll
            for (int i = 0; i < 8; i++)
                eA[i] = *(const float4*)&ep2[i * 128 + lane * 4];
        }
        process(eB, t0 + tt + 1);
        ep = ep2;
    }

    float* cp = &g_ctxpart[((size_t)b * 64 + seg) * HH];
#pragma unroll
    for (int i = 0; i < 8; i++)
        *(float4*)&cp[i * 128 + lane * 4] = cc[i];
    if (lane == 0) {
        g_mpart[b * 64 + seg] = m;
        g_lpart[b * 64 + seg] = l;
    }
}

// ---------------- combine partials -> context, y, attn probs ----------------
__global__ __launch_bounds__(256) void attn_combine_kernel(
        float* __restrict__ ctx_out, float* __restrict__ attn_out) {
    int b = blockIdx.x;
    int tid = threadIdx.x;
    __shared__ float sm[64], sl[64], sw[64];
    __shared__ float sML[2];
    if (tid < 64) {
        sm[tid] = g_mpart[b * 64 + tid];
        sl[tid] = g_lpart[b * 64 + tid];
    }
    __syncthreads();
    if (tid == 0) {
        float M = -1e30f;
        for (int s = 0; s < 64; s++) M = fmaxf(M, sm[s]);
        float L = 0.f;
        for (int s = 0; s < 64; s++) L += sl[s] * __expf(sm[s] - M);
        sML[0] = M; sML[1] = L;
    }
    __syncthreads();
    if (tid < 64) sw[tid] = __expf(sm[tid] - sML[0]) / sML[1];
    __syncthreads();

    int h = tid * 4;
    float4 a = make_float4(0.f, 0.f, 0.f, 0.f);
    for (int s = 0; s < 64; s++) {
        float4 v = *(const float4*)&g_ctxpart[((size_t)b * 64 + s) * HH + h];
        float w = sw[s];
        a.x += w * v.x; a.y += w * v.y; a.z += w * v.z; a.w += w * v.w;
    }
    *(float4*)&ctx_out[b * HH + h] = a;
    *(float4*)&g_y[b * 2 * HH + HH + h] = a;

    const float M = sML[0], L = sML[1];
    for (int t = tid; t < TT; t += 256)
        attn_out[b * TT + t] = __expf(g_scores[b * TT + t] - M) / L;
}

// ---------------- out = logits - lse ----------------
__global__ __launch_bounds__(256) void out_write_kernel(float* __restrict__ out) {
    int idx = blockIdx.x * blockDim.x + threadIdx.x;
    if (idx >= BB * VV) return;
    int b = idx / VV;
    out[idx] = g_logits[idx] - g_lse[b];
}

// ---------------- launch ----------------
extern "C" void kernel_launch(void* const* d_in, const int* in_sizes, int n_in,
                              void* d_out, int out_size) {
    const int*   inputs  = (const int*)d_in[0];
    const float* hidden  = (const float*)d_in[1];
    const float* context = (const float*)d_in[2];
    const float* enc     = (const float*)d_in[3];
    const float* E       = (const float*)d_in[4];
    const float* W_ih0   = (const float*)d_in[5];
    const float* W_hh0   = (const float*)d_in[6];
    const float* b_ih0   = (const float*)d_in[7];
    const float* b_hh0   = (const float*)d_in[8];
    const float* W_ih1   = (const float*)d_in[9];
    const float* W_hh1   = (const float*)d_in[10];
    const float* b_ih1   = (const float*)d_in[11];
    const float* b_hh1   = (const float*)d_in[12];
    const float* Wa      = (const float*)d_in[13];
    // d_in[14] = ba: softmax-invariant per-batch constant -> unused
    const float* Wo      = (const float*)d_in[15];
    const float* bo      = (const float*)d_in[16];

    float* out0     = (float*)d_out;
    float* hid_out  = out0 + (size_t)BB * VV;
    float* ctx_out  = hid_out + 2 * BB * HH;
    float* attn_out = ctx_out + BB * HH;

    void *p_x, *p_gi, *p_gia, *p_gib, *p_gic, *p_gh, *p_gha, *p_gh1, *p_gh1a;
    void *p_h0, *p_h1, *p_up, *p_y, *p_logits;
    cudaGetSymbolAddress(&p_x, g_x);
    cudaGetSymbolAddress(&p_gi, g_gi);
    cudaGetSymbolAddress(&p_gia, g_gia);
    cudaGetSymbolAddress(&p_gib, g_gib);
    cudaGetSymbolAddress(&p_gic, g_gic);
    cudaGetSymbolAddress(&p_gh, g_gh);
    cudaGetSymbolAddress(&p_gha, g_gha);
    cudaGetSymbolAddress(&p_gh1, g_gh1);
    cudaGetSymbolAddress(&p_gh1a, g_gh1a);
    cudaGetSymbolAddress(&p_h0, g_h0);
    cudaGetSymbolAddress(&p_h1, g_h1);
    cudaGetSymbolAddress(&p_up, g_up);
    cudaGetSymbolAddress(&p_y, g_y);
    cudaGetSymbolAddress(&p_logits, g_logits);
    float* xx   = (float*)p_x;
    float* gi   = (float*)p_gi;
    float* gia  = (float*)p_gia;
    float* gib  = (float*)p_gib;
    float* gic  = (float*)p_gic;
    float* gh   = (float*)p_gh;
    float* gha  = (float*)p_gha;
    float* gh1  = (float*)p_gh1;
    float* gh1a = (float*)p_gh1a;
    float* h0   = (float*)p_h0;
    float* h1   = (float*)p_h1;
    float* up   = (float*)p_up;
    float* yy   = (float*)p_y;
    float* lg   = (float*)p_logits;

    static bool attr_done = false;
    if (!attr_done) {
        cudaFuncSetAttribute(gemm_multi_kernel<false>,
                             cudaFuncAttributeMaxDynamicSharedMemorySize, GEMM_SMEM_BYTES);
        cudaFuncSetAttribute(gemm_multi_kernel<true>,
                             cudaFuncAttributeMaxDynamicSharedMemorySize, GEMM_SMEM_BYTES);
        cudaFuncSetAttribute(gemm_wo_kernel,
                             cudaFuncAttributeMaxDynamicSharedMemorySize, WO_SMEM_BYTES);
        attr_done = true;
    }

    const int HK = HH / 2;   // 512 split-K chunk

    // 1) x = concat(E[inputs], context)
    build_x_kernel<<<(BB * 2 * HH) / 256, 256>>>(inputs, E, context);

    // 2) G1: 8 problems, grid 384: gi0 (emb/ctx each split-K=2), gh0 x2, gh1 x2
    {
        Probs8 P;
        P.p[0] = { xx,                 W_ih0,                     gi,   2 * HH, 2 * HH, 3 * HH, HK };
        P.p[1] = { xx + HK,            W_ih0 + HK,                gia,  2 * HH, 2 * HH, 3 * HH, HK };
        P.p[2] = { xx + HH,            W_ih0 + HH,                gib,  2 * HH, 2 * HH, 3 * HH, HK };
        P.p[3] = { xx + HH + HK,       W_ih0 + HH + HK,           gic,  2 * HH, 2 * HH, 3 * HH, HK };
        P.p[4] = { hidden,             W_hh0,                     gh,   HH,     HH,     3 * HH, HK };
        P.p[5] = { hidden + HK,        W_hh0 + HK,                gha,  HH,     HH,     3 * HH, HK };
        P.p[6] = { hidden + BB * HH,        W_hh1,                gh1,  HH,     HH,     3 * HH, HK };
        P.p[7] = { hidden + BB * HH + HK,   W_hh1 + HK,           gh1a, HH,     HH,     3 * HH, HK };
        gemm_multi_kernel<false><<<dim3(48, 8), 256, GEMM_SMEM_BYTES>>>(P);
    }
    gru_gates_kernel<<<(BB * HH) / 256, 256>>>(gi, gia, gib, gic, b_ih0,
                                               gh, gha, b_hh0,
                                               hidden, h0, hid_out, nullptr);

    // 3) G2: gi1 split-K=4 — grid 192 (gh1 partials already computed in G1)
    {
        Probs8 P;
        for (int i = 0; i < 4; i++) {
            float* dst = (i == 0) ? gi : (i == 1) ? gia : (i == 2) ? gib : gic;
            P.p[i] = { h0 + i * 256, W_ih1 + i * 256, dst, HH, HH, 3 * HH, 256 };
        }
        for (int i = 4; i < 8; i++) P.p[i] = P.p[0];
        gemm_multi_kernel<false><<<dim3(48, 4), 256, GEMM_SMEM_BYTES>>>(P);
    }
    gru_gates_kernel<<<(BB * HH) / 256, 256>>>(gi, gia, gib, gic, b_ih1,
                                               gh1, gh1a, b_hh1,
                                               hidden + BB * HH, h1,
                                               hid_out + BB * HH, yy);

    // 4) u = h1 @ Wa, split-K=8 — grid 128 (Wa is [K,N] -> TRANS), nk=4
    {
        Probs8 P;
        for (int i = 0; i < 8; i++) {
            P.p[i] = { h1 + i * 128, Wa + (size_t)(i * 128) * HH,
                       up + (size_t)i * BB * HH, HH, HH, HH, 128 };
        }
        gemm_multi_kernel<true><<<dim3(16, 8), 256, GEMM_SMEM_BYTES>>>(P);
    }
    u_reduce_kernel<<<(BB * HH / 4) / 256, 256>>>();

    // 5) flash-attention pass + fused combine/attn-prob write
    attn_partial_kernel<<<dim3(16, BB), 128>>>(enc);
    attn_combine_kernel<<<BB, 256>>>(ctx_out, attn_out);

    // 6) logits = tanh(y @ Wo^T + bo), fused LSE partials — grid 393
    gemm_wo_kernel<<<NWO, 256, WO_SMEM_BYTES>>>(yy, Wo, bo, lg);

    // 7) log_softmax epilogue
    lse_combine_kernel<<<BB, 128>>>();
    out_write_kernel<<<(BB * VV + 255) / 256, 256>>>(out0);
}